// round 13
// baseline (speedup 1.0000x reference)
#include <cuda_runtime.h>
#include <cuda_fp16.h>
#include <math.h>
#include <stdint.h>

// ---------------------------------------------------------------------------
// DinoDecoderBlock: B=8, NQ=NK=1024, C=768, H=12, HD=64, HID=3072
// Round 13: revert R12's aproj/cproj split-K (fill overhead > quantization
// saving at K=768); keep fc2 split-K. NEW: 4-stage cp.async GEMM pipeline
// (each load group gets ~3 compute iters of latency budget instead of 1).
// ---------------------------------------------------------------------------

#define Bb   8
#define NQ   1024
#define NKk  1024
#define Cc   768
#define Hh   12
#define HD   64
#define HID  3072
#define MROWS (Bb*NQ)          // 8192
#define SCALE 0.125f

// ------------------------- scratch (no allocs allowed) ---------------------
__device__ float g_x1   [(size_t)MROWS*Cc];
__device__ float g_x2   [(size_t)MROWS*Cc];

__device__ __half g_qkvh [(size_t)MROWS*3*Cc];
__device__ __half g_qh   [(size_t)MROWS*Cc];
__device__ __half g_kvh  [(size_t)MROWS*2*Cc];

__device__ __half g_ln  [(size_t)MROWS*Cc];
__device__ __half g_yln [(size_t)MROWS*Cc];
__device__ __half g_ao  [(size_t)MROWS*Cc];
__device__ __half g_h1  [(size_t)MROWS*HID];

#define W_QKV   0u
#define W_APROJ 1769472u
#define W_Q     2359296u
#define W_K     2949120u
#define W_V     3538944u
#define W_CPROJ 4128768u
#define W_FC1   4718592u
#define W_FC2   7077888u
#define W_TOT   9437184u
__device__ __half g_w[W_TOT];

__device__ unsigned char g_mask[(size_t)NQ*NKk];
__device__ int g_mask_is_u8;

// --------------------------- PTX helpers -----------------------------------
__device__ __forceinline__ uint32_t smem_u32(const void* p) {
    uint32_t a;
    asm("{ .reg .u64 t; cvta.to.shared.u64 t, %1; cvt.u32.u64 %0, t; }"
        : "=r"(a) : "l"(p));
    return a;
}
__device__ __forceinline__ void cp16(uint32_t dst, const void* src) {
    asm volatile("cp.async.cg.shared.global [%0], [%1], 16;" :: "r"(dst), "l"(src));
}
#define CP_COMMIT() asm volatile("cp.async.commit_group;" ::: "memory")
#define CP_WAIT(n)  asm volatile("cp.async.wait_group %0;" :: "n"(n) : "memory")

__device__ __forceinline__ void ldm_x4(uint32_t* r, uint32_t addr) {
    asm volatile("ldmatrix.sync.aligned.m8n8.x4.shared.b16 {%0,%1,%2,%3}, [%4];"
                 : "=r"(r[0]), "=r"(r[1]), "=r"(r[2]), "=r"(r[3]) : "r"(addr));
}
__device__ __forceinline__ void ldm_x2(uint32_t* r, uint32_t addr) {
    asm volatile("ldmatrix.sync.aligned.m8n8.x2.shared.b16 {%0,%1}, [%2];"
                 : "=r"(r[0]), "=r"(r[1]) : "r"(addr));
}
__device__ __forceinline__ void ldm_x2t(uint32_t* r, uint32_t addr) {
    asm volatile("ldmatrix.sync.aligned.m8n8.x2.trans.shared.b16 {%0,%1}, [%2];"
                 : "=r"(r[0]), "=r"(r[1]) : "r"(addr));
}
__device__ __forceinline__ void mma_f16(float* d, const uint32_t* a, const uint32_t* b) {
    asm volatile(
        "mma.sync.aligned.m16n8k16.row.col.f32.f16.f16.f32 "
        "{%0,%1,%2,%3}, {%4,%5,%6,%7}, {%8,%9}, {%0,%1,%2,%3};"
        : "+f"(d[0]), "+f"(d[1]), "+f"(d[2]), "+f"(d[3])
        : "r"(a[0]), "r"(a[1]), "r"(a[2]), "r"(a[3]), "r"(b[0]), "r"(b[1]));
}
__device__ __forceinline__ uint32_t packh(float a, float b) {
    __half2 t = __floats2half2_rn(a, b);
    return *(uint32_t*)&t;
}
__device__ __forceinline__ void red2f(float* p, float v0, float v1) {
    asm volatile("red.global.add.v2.f32 [%0], {%1, %2};"
                 :: "l"(p), "f"(v0), "f"(v1) : "memory");
}

// --------------------------- weight convert --------------------------------
__global__ void wconvert_all(
    const float* __restrict__ s0, const float* __restrict__ s1,
    const float* __restrict__ s2, const float* __restrict__ s3,
    const float* __restrict__ s4, const float* __restrict__ s5,
    const float* __restrict__ s6, const float* __restrict__ s7)
{
    unsigned int i = blockIdx.x * blockDim.x + threadIdx.x;
    if (i >= W_TOT) return;
    float v;
    if      (i < W_APROJ) v = s0[i - W_QKV];
    else if (i < W_Q)     v = s1[i - W_APROJ];
    else if (i < W_K)     v = s2[i - W_Q];
    else if (i < W_V)     v = s3[i - W_K];
    else if (i < W_CPROJ) v = s4[i - W_V];
    else if (i < W_FC1)   v = s5[i - W_CPROJ];
    else if (i < W_FC2)   v = s6[i - W_FC1];
    else                  v = s7[i - W_FC2];
    g_w[i] = __float2half_rn(v);
}

// --------------------------- mask detect/decode ----------------------------
__global__ void mask_detect(const unsigned int* __restrict__ m)
{
    __shared__ int flag;
    if (threadIdx.x == 0) flag = 0;
    __syncthreads();
    for (int i = threadIdx.x; i < 65536; i += blockDim.x)
        if (m[i] > 1u) flag = 1;
    __syncthreads();
    if (threadIdx.x == 0) g_mask_is_u8 = flag;
}
__global__ void mask_decode(const void* __restrict__ msrc)
{
    size_t i = (size_t)blockIdx.x * blockDim.x + threadIdx.x;
    if (i >= (size_t)NQ * NKk) return;
    unsigned char v;
    if (g_mask_is_u8) v = ((const unsigned char*)msrc)[i] ? 1 : 0;
    else              v = ((const int*)msrc)[i] ? 1 : 0;
    g_mask[i] = v;
}

// ------------------------------ LayerNorm ----------------------------------
__global__ void ln_kernel(const float* __restrict__ X, const float* __restrict__ g,
                          const float* __restrict__ b, __half* __restrict__ O)
{
    int row = blockIdx.x;
    const float* x = X + (size_t)row * Cc;
    int t = threadIdx.x;
    float v0 = x[t], v1 = x[t + 256], v2 = x[t + 512];
    float s  = v0 + v1 + v2;
    float s2 = v0*v0 + v1*v1 + v2*v2;
    #pragma unroll
    for (int off = 16; off; off >>= 1) {
        s  += __shfl_xor_sync(0xffffffffu, s,  off);
        s2 += __shfl_xor_sync(0xffffffffu, s2, off);
    }
    __shared__ float shs[8], shs2[8];
    int w = t >> 5, l = t & 31;
    if (l == 0) { shs[w] = s; shs2[w] = s2; }
    __syncthreads();
    if (w == 0) {
        s  = (l < 8) ? shs[l]  : 0.f;
        s2 = (l < 8) ? shs2[l] : 0.f;
        #pragma unroll
        for (int off = 4; off; off >>= 1) {
            s  += __shfl_xor_sync(0xffffffffu, s,  off);
            s2 += __shfl_xor_sync(0xffffffffu, s2, off);
        }
        if (l == 0) { shs[0] = s; shs2[0] = s2; }
    }
    __syncthreads();
    float mean = shs[0] * (1.f / Cc);
    float var  = shs2[0] * (1.f / Cc) - mean * mean;
    float inv  = rsqrtf(var + 1e-5f);
    size_t base = (size_t)row * Cc;
    #pragma unroll
    for (int j = 0; j < 3; j++) {
        int c = t + j * 256;
        float v = (j == 0 ? v0 : (j == 1 ? v1 : v2));
        O[base + c] = __float2half_rn((v - mean) * inv * g[c] + b[c]);
    }
}

// ------------------ output init (for split-K accumulation) ------------------
__global__ void init_out(const float4* __restrict__ src, const float* __restrict__ bias,
                         float4* __restrict__ dst)
{
    int i = blockIdx.x * blockDim.x + threadIdx.x;
    if (i >= MROWS * Cc / 4) return;
    int c4 = (i % (Cc / 4)) * 4;
    float4 v = src[i];
    v.x += bias[c4];
    v.y += bias[c4 + 1];
    v.z += bias[c4 + 2];
    v.w += bias[c4 + 3];
    dst[i] = v;
}

// --------------------------- HMMA GEMM 128x128, 4-stage ---------------------
#define PADR 40
#define TILE_B (128 * PADR * 2)       // 10240 bytes
#define STAGE_B (2 * TILE_B)          // 20480 bytes
#define GSM_TOTAL (4 * STAGE_B)       // 81920 bytes

__global__ void __launch_bounds__(256, 2) gemm_tc(
    const __half* __restrict__ Ah, const __half* __restrict__ Bw,
    int Kstride, int Klen, int N,
    const float* __restrict__ bias, const float* __restrict__ res, int gelu,
    float* __restrict__ outF, __half* __restrict__ outH, int atomicF)
{
    extern __shared__ char smem[];
    uint32_t smb = smem_u32(smem);
    int tid = threadIdx.x;
    int wid = tid >> 5, lane = tid & 31;
    int wm = wid >> 2, wn = wid & 3;
    int m0 = blockIdx.y * 128;
    int n0 = blockIdx.x * 128;
    int kOff = blockIdx.z * Klen;

    int lr0 = tid >> 2;
    int lc  = (tid & 3) << 3;

    float acc[4][4][4];
    #pragma unroll
    for (int i = 0; i < 4; i++)
        #pragma unroll
        for (int j = 0; j < 4; j++)
            #pragma unroll
            for (int r = 0; r < 4; r++) acc[i][j][r] = 0.f;

    int NIT = Klen >> 5;   // >= 12 for all call sites

    auto load_stage = [&](int it, int s) {
        int k0 = kOff + (it << 5);
        uint32_t sb = smb + s * STAGE_B;
        #pragma unroll
        for (int tgt = 0; tgt < 2; tgt++) {
            const __half* base = (tgt == 0 ? Ah + (size_t)m0 * Kstride
                                           : Bw + (size_t)n0 * Kstride) + k0;
            uint32_t tb = sb + tgt * TILE_B;
            #pragma unroll
            for (int q = 0; q < 2; q++) {
                int row = lr0 + q * 64;
                cp16(tb + (uint32_t)(row * PADR + lc) * 2,
                     base + (size_t)row * Kstride + lc);
            }
        }
    };

    load_stage(0, 0);
    CP_COMMIT();
    load_stage(1, 1);
    CP_COMMIT();
    load_stage(2, 2);
    CP_COMMIT();

    int s = 0;
    for (int it = 0; it < NIT; it++) {
        int rem = NIT - 1 - it;     // committed groups after group `it`
        if (rem >= 2)      CP_WAIT(2);
        else if (rem == 1) CP_WAIT(1);
        else               CP_WAIT(0);
        __syncthreads();
        if (it + 3 < NIT) {
            int s3 = s + 3; if (s3 >= 4) s3 -= 4;
            load_stage(it + 3, s3);
            CP_COMMIT();
        }

        uint32_t sA = smb + s * STAGE_B;
        uint32_t sB = sA + TILE_B;

        #pragma unroll
        for (int kk = 0; kk < 32; kk += 16) {
            uint32_t ah[4][4], bw[4][2];
            int arow = lane & 15;
            int acol = kk + ((lane >> 4) << 3);
            #pragma unroll
            for (int i = 0; i < 4; i++) {
                uint32_t off = (uint32_t)((wm * 64 + i * 16 + arow) * PADR + acol) * 2;
                ldm_x4(ah[i], sA + off);
            }
            int brow = lane & 7;
            int bcol = kk + ((lane >> 3) & 1) * 8;
            #pragma unroll
            for (int j = 0; j < 4; j++) {
                uint32_t off = (uint32_t)((wn * 32 + j * 8 + brow) * PADR + bcol) * 2;
                ldm_x2(bw[j], sB + off);
            }
            #pragma unroll
            for (int i = 0; i < 4; i++)
                #pragma unroll
                for (int j = 0; j < 4; j++)
                    mma_f16(acc[i][j], ah[i], bw[j]);
        }
        if (++s >= 4) s = 0;
    }

    #pragma unroll
    for (int i = 0; i < 4; i++) {
        #pragma unroll
        for (int j = 0; j < 4; j++) {
            int mb = m0 + wm * 64 + i * 16 + (lane >> 2);
            int nb = n0 + wn * 32 + j * 8 + (lane & 3) * 2;
            #pragma unroll
            for (int half = 0; half < 2; half++) {
                int m = mb + half * 8;
                float v0 = acc[i][j][half * 2 + 0];
                float v1 = acc[i][j][half * 2 + 1];
                size_t gi = (size_t)m * N + nb;
                if (atomicF) {
                    red2f(outF + gi, v0, v1);
                    continue;
                }
                if (bias) { v0 += bias[nb]; v1 += bias[nb + 1]; }
                if (gelu) {
                    v0 = 0.5f * v0 * (1.0f + erff(v0 * 0.70710678118654752f));
                    v1 = 0.5f * v1 * (1.0f + erff(v1 * 0.70710678118654752f));
                }
                if (res) {
                    float2 r2 = *(const float2*)(res + gi);
                    v0 += r2.x; v1 += r2.y;
                }
                if (outF) {
                    float2 o2 = make_float2(v0, v1);
                    *(float2*)(outF + gi) = o2;
                }
                if (outH) {
                    __half2 hh = __floats2half2_rn(v0, v1);
                    *(__half2*)(outH + gi) = hh;
                }
            }
        }
    }
}

// --------------------------- flash attention (fp16) -------------------------
#define FA_PAD 72
#define FS_Q  0u
#define FS_K  18432u
#define FS_V  36864u
#define FS_M  55296u
#define FA_SMEM 71680u

__global__ void __launch_bounds__(256, 2) flash_attn(
    const __half* __restrict__ Qsrc, const __half* __restrict__ Ksrc,
    const __half* __restrict__ Vsrc,
    size_t qBatch, size_t kvBatch, int qStride, int kvStride,
    const unsigned char* __restrict__ maskp,
    __half* __restrict__ Oh)
{
    extern __shared__ char smem[];
    uint32_t smb = smem_u32(smem);
    int tid = threadIdx.x;
    int wid = tid >> 5, lane = tid & 31;
    int wq = wid << 4;
    int bh = blockIdx.y;
    int b = bh / Hh, h = bh % Hh;
    int qrow0 = blockIdx.x * 128;

    const __half* Qb = Qsrc + (size_t)b * qBatch + h * HD;
    const __half* Kb = Ksrc + (size_t)b * kvBatch + h * HD;
    const __half* Vb = Vsrc + (size_t)b * kvBatch + h * HD;

    auto load_kv = [&](int t, int s) {
        #pragma unroll
        for (int j2 = 0; j2 < 2; j2++) {
            int idx = tid + j2 * 256;
            int r = idx >> 3, c = (idx & 7) << 3;
            cp16(smb + FS_K + s * 9216u + (uint32_t)(r * FA_PAD + c) * 2,
                 Kb + (size_t)(t * 64 + r) * kvStride + c);
            cp16(smb + FS_V + s * 9216u + (uint32_t)(r * FA_PAD + c) * 2,
                 Vb + (size_t)(t * 64 + r) * kvStride + c);
        }
        if (maskp) {
            #pragma unroll
            for (int j2 = 0; j2 < 2; j2++) {
                int idx = tid + j2 * 256;
                int r = idx >> 2, c = (idx & 3) << 4;
                cp16(smb + FS_M + s * 8192u + (uint32_t)(r * 64 + c),
                     maskp + (size_t)(qrow0 + r) * NKk + t * 64 + c);
            }
        }
    };

    #pragma unroll
    for (int j4 = 0; j4 < 4; j4++) {
        int idx = tid + j4 * 256;
        int r = idx >> 3, c = (idx & 7) << 3;
        cp16(smb + FS_Q + (uint32_t)(r * FA_PAD + c) * 2,
             Qb + (size_t)(qrow0 + r) * qStride + c);
    }
    load_kv(0, 0);
    CP_COMMIT();

    uint32_t Aq[4][4];
    float O[8][4];
    #pragma unroll
    for (int j = 0; j < 8; j++)
        #pragma unroll
        for (int e = 0; e < 4; e++) O[j][e] = 0.f;
    float m0 = -1e30f, m1 = -1e30f, l0 = 0.f, l1 = 0.f;

    int r0l = wq + (lane >> 2);
    int cb2 = (lane & 3) * 2;

    for (int t = 0; t < 16; t++) {
        int s = t & 1;
        if (t + 1 < 16) {
            load_kv(t + 1, s ^ 1);
            CP_COMMIT();
            CP_WAIT(1);
        } else {
            CP_WAIT(0);
        }
        __syncthreads();

        if (t == 0) {
            #pragma unroll
            for (int kc = 0; kc < 4; kc++) {
                uint32_t off = (uint32_t)((wq + (lane & 15)) * FA_PAD
                               + kc * 16 + ((lane >> 4) << 3)) * 2;
                ldm_x4(Aq[kc], smb + FS_Q + off);
            }
        }

        float S[8][4];
        #pragma unroll
        for (int j = 0; j < 8; j++)
            #pragma unroll
            for (int e = 0; e < 4; e++) S[j][e] = 0.f;
        uint32_t sK = smb + FS_K + s * 9216u;
        #pragma unroll
        for (int kc = 0; kc < 4; kc++) {
            #pragma unroll
            for (int j = 0; j < 8; j++) {
                uint32_t bk[2];
                uint32_t off = (uint32_t)((8 * j + (lane & 7)) * FA_PAD
                               + 16 * kc + ((lane >> 3) & 1) * 8) * 2;
                ldm_x2(bk, sK + off);
                mma_f16(S[j], Aq[kc], bk);
            }
        }

        const unsigned char* sM = (const unsigned char*)(smem + FS_M + s * 8192u);
        #pragma unroll
        for (int j = 0; j < 8; j++) {
            S[j][0] *= SCALE; S[j][1] *= SCALE;
            S[j][2] *= SCALE; S[j][3] *= SCALE;
            if (maskp) {
                int col = 8 * j + cb2;
                unsigned short mw0 = *(const unsigned short*)(sM + r0l * 64 + col);
                unsigned short mw1 = *(const unsigned short*)(sM + (r0l + 8) * 64 + col);
                if (!(mw0 & 0xFF))   S[j][0] = -1e9f;
                if (!(mw0 >> 8))     S[j][1] = -1e9f;
                if (!(mw1 & 0xFF))   S[j][2] = -1e9f;
                if (!(mw1 >> 8))     S[j][3] = -1e9f;
            }
        }

        float mx0 = -1e30f, mx1 = -1e30f;
        #pragma unroll
        for (int j = 0; j < 8; j++) {
            mx0 = fmaxf(mx0, fmaxf(S[j][0], S[j][1]));
            mx1 = fmaxf(mx1, fmaxf(S[j][2], S[j][3]));
        }
        mx0 = fmaxf(mx0, __shfl_xor_sync(0xffffffffu, mx0, 1));
        mx0 = fmaxf(mx0, __shfl_xor_sync(0xffffffffu, mx0, 2));
        mx1 = fmaxf(mx1, __shfl_xor_sync(0xffffffffu, mx1, 1));
        mx1 = fmaxf(mx1, __shfl_xor_sync(0xffffffffu, mx1, 2));
        float mn0 = fmaxf(m0, mx0), mn1 = fmaxf(m1, mx1);
        float a0 = __expf(m0 - mn0), a1 = __expf(m1 - mn1);
        float sum0 = 0.f, sum1 = 0.f;
        #pragma unroll
        for (int j = 0; j < 8; j++) {
            S[j][0] = __expf(S[j][0] - mn0); sum0 += S[j][0];
            S[j][1] = __expf(S[j][1] - mn0); sum0 += S[j][1];
            S[j][2] = __expf(S[j][2] - mn1); sum1 += S[j][2];
            S[j][3] = __expf(S[j][3] - mn1); sum1 += S[j][3];
        }
        l0 = l0 * a0 + sum0;
        l1 = l1 * a1 + sum1;
        m0 = mn0; m1 = mn1;
        #pragma unroll
        for (int j = 0; j < 8; j++) {
            O[j][0] *= a0; O[j][1] *= a0;
            O[j][2] *= a1; O[j][3] *= a1;
        }

        uint32_t sV = smb + FS_V + s * 9216u;
        #pragma unroll
        for (int kc = 0; kc < 4; kc++) {
            uint32_t Ap[4];
            Ap[0] = packh(S[2 * kc][0],     S[2 * kc][1]);
            Ap[1] = packh(S[2 * kc][2],     S[2 * kc][3]);
            Ap[2] = packh(S[2 * kc + 1][0], S[2 * kc + 1][1]);
            Ap[3] = packh(S[2 * kc + 1][2], S[2 * kc + 1][3]);
            #pragma unroll
            for (int j = 0; j < 8; j++) {
                uint32_t bv[2];
                uint32_t off = (uint32_t)((16 * kc + (lane & 15)) * FA_PAD + 8 * j) * 2;
                ldm_x2t(bv, sV + off);
                mma_f16(O[j], Ap, bv);
            }
        }
        __syncthreads();
    }

    l0 += __shfl_xor_sync(0xffffffffu, l0, 1);
    l0 += __shfl_xor_sync(0xffffffffu, l0, 2);
    l1 += __shfl_xor_sync(0xffffffffu, l1, 1);
    l1 += __shfl_xor_sync(0xffffffffu, l1, 2);
    float inv0 = 1.f / l0, inv1 = 1.f / l1;
    int grow0 = qrow0 + r0l;
    size_t obase = (size_t)b * NQ * Cc + (size_t)h * HD;
    #pragma unroll
    for (int j = 0; j < 8; j++) {
        int col = 8 * j + cb2;
        size_t gi0 = obase + (size_t)grow0 * Cc + col;
        *(__half2*)(Oh + gi0) = __floats2half2_rn(O[j][0] * inv0, O[j][1] * inv0);
        size_t gi1 = obase + (size_t)(grow0 + 8) * Cc + col;
        *(__half2*)(Oh + gi1) = __floats2half2_rn(O[j][2] * inv1, O[j][3] * inv1);
    }
}

// ------------------------------ copy (y) -----------------------------------
__global__ void copy4_kernel(const float4* __restrict__ src, float4* __restrict__ dst, int n4)
{
    int i = blockIdx.x * blockDim.x + threadIdx.x;
    if (i < n4) dst[i] = src[i];
}

// ----------------------------- launch --------------------------------------
extern "C" void kernel_launch(void* const* d_in, const int* in_sizes, int n_in,
                              void* d_out, int out_size)
{
    const float* x        = (const float*)d_in[0];
    const float* y        = (const float*)d_in[1];
    const void*  mask_raw = d_in[4];
    const float* qkv_w    = (const float*)d_in[5];
    const float* aproj_w  = (const float*)d_in[6];
    const float* aproj_b  = (const float*)d_in[7];
    const float* q_w      = (const float*)d_in[8];
    const float* k_w      = (const float*)d_in[9];
    const float* v_w      = (const float*)d_in[10];
    const float* cproj_w  = (const float*)d_in[11];
    const float* cproj_b  = (const float*)d_in[12];
    const float* fc1_w    = (const float*)d_in[13];
    const float* fc1_b    = (const float*)d_in[14];
    const float* fc2_w    = (const float*)d_in[15];
    const float* fc2_b    = (const float*)d_in[16];
    const float* ln1_g    = (const float*)d_in[17];
    const float* ln1_b    = (const float*)d_in[18];
    const float* ln2_g    = (const float*)d_in[19];
    const float* ln2_b    = (const float*)d_in[20];
    const float* ln3_g    = (const float*)d_in[21];
    const float* ln3_b    = (const float*)d_in[22];
    const float* lny_g    = (const float*)d_in[23];
    const float* lny_b    = (const float*)d_in[24];
    float* out = (float*)d_out;

    float *p_x1, *p_x2;
    __half *p_qkvh, *p_qh, *p_kvh, *p_ln, *p_yln, *p_ao, *p_h1, *p_w;
    unsigned char* p_mask;
    cudaGetSymbolAddress((void**)&p_x1,  g_x1);
    cudaGetSymbolAddress((void**)&p_x2,  g_x2);
    cudaGetSymbolAddress((void**)&p_qkvh, g_qkvh);
    cudaGetSymbolAddress((void**)&p_qh,  g_qh);
    cudaGetSymbolAddress((void**)&p_kvh, g_kvh);
    cudaGetSymbolAddress((void**)&p_ln,  g_ln);
    cudaGetSymbolAddress((void**)&p_yln, g_yln);
    cudaGetSymbolAddress((void**)&p_ao,  g_ao);
    cudaGetSymbolAddress((void**)&p_h1,  g_h1);
    cudaGetSymbolAddress((void**)&p_w,   g_w);
    cudaGetSymbolAddress((void**)&p_mask, g_mask);

    cudaFuncSetAttribute(gemm_tc, cudaFuncAttributeMaxDynamicSharedMemorySize, GSM_TOTAL);
    cudaFuncSetAttribute(flash_attn, cudaFuncAttributeMaxDynamicSharedMemorySize, FA_SMEM);

    static cudaStream_t s1 = nullptr;
    static cudaEvent_t evFork = nullptr, evW = nullptr, evKV = nullptr;
    static cudaEvent_t evX2 = nullptr, evInit = nullptr;
    if (!s1) {
        cudaStreamCreateWithFlags(&s1, cudaStreamNonBlocking);
        cudaEventCreateWithFlags(&evFork, cudaEventDisableTiming);
        cudaEventCreateWithFlags(&evW, cudaEventDisableTiming);
        cudaEventCreateWithFlags(&evKV, cudaEventDisableTiming);
        cudaEventCreateWithFlags(&evX2, cudaEventDisableTiming);
        cudaEventCreateWithFlags(&evInit, cudaEventDisableTiming);
    }

    dim3 t256(256);
    dim3 gFlash(NQ / 128, Bb * Hh);
    int nInit = (MROWS * Cc / 4 + 255) / 256;

    // ---- fork ----
    cudaEventRecord(evFork, 0);
    cudaStreamWaitEvent(s1, evFork, 0);

    // ---- stream s1: weights, mask, y-branch ----
    wconvert_all<<<(W_TOT + 255) / 256, t256, 0, s1>>>(
        qkv_w, aproj_w, q_w, k_w, v_w, cproj_w, fc1_w, fc2_w);
    cudaEventRecord(evW, s1);
    mask_detect<<<1, 256, 0, s1>>>((const unsigned int*)mask_raw);
    mask_decode<<<(NQ * NKk + 255) / 256, t256, 0, s1>>>(mask_raw);
    ln_kernel<<<MROWS, t256, 0, s1>>>(y, lny_g, lny_b, p_yln);
    gemm_tc<<<dim3(2 * Cc / 128, MROWS / 128), t256, GSM_TOTAL, s1>>>(
        p_yln, p_w + W_K, Cc, Cc, 2 * Cc,
        nullptr, nullptr, 0, nullptr, p_kvh, 0);
    {
        int n4 = (MROWS * Cc) / 4;
        copy4_kernel<<<(n4 + 255) / 256, t256, 0, s1>>>((const float4*)y,
            (float4*)(out + (size_t)MROWS * Cc), n4);
    }
    cudaEventRecord(evKV, s1);

    // ---- stream 0: x-chain ----
    ln_kernel<<<MROWS, t256>>>(x, ln1_g, ln1_b, p_ln);
    cudaStreamWaitEvent(0, evW, 0);
    gemm_tc<<<dim3(3 * Cc / 128, MROWS / 128), t256, GSM_TOTAL>>>(
        p_ln, p_w + W_QKV, Cc, Cc, 3 * Cc,
        nullptr, nullptr, 0, nullptr, p_qkvh, 0);
    flash_attn<<<gFlash, t256, FA_SMEM>>>(
        p_qkvh, p_qkvh + Cc, p_qkvh + 2 * Cc,
        (size_t)NQ * 3 * Cc, (size_t)NQ * 3 * Cc, 3 * Cc, 3 * Cc,
        nullptr, p_ao);
    gemm_tc<<<dim3(Cc / 128, MROWS / 128), t256, GSM_TOTAL>>>(
        p_ao, p_w + W_APROJ, Cc, Cc, Cc,
        aproj_b, x, 0, p_x1, nullptr, 0);

    // ---- cross attention ----
    ln_kernel<<<MROWS, t256>>>(p_x1, ln2_g, ln2_b, p_ln);
    gemm_tc<<<dim3(Cc / 128, MROWS / 128), t256, GSM_TOTAL>>>(
        p_ln, p_w + W_Q, Cc, Cc, Cc,
        nullptr, nullptr, 0, nullptr, p_qh, 0);
    cudaStreamWaitEvent(0, evKV, 0);
    flash_attn<<<gFlash, t256, FA_SMEM>>>(
        p_qh, p_kvh, p_kvh + Cc,
        (size_t)NQ * Cc, (size_t)NKk * 2 * Cc, Cc, 2 * Cc,
        p_mask, p_ao);
    gemm_tc<<<dim3(Cc / 128, MROWS / 128), t256, GSM_TOTAL>>>(
        p_ao, p_w + W_CPROJ, Cc, Cc, Cc,
        cproj_b, p_x1, 0, p_x2, nullptr, 0);
    cudaEventRecord(evX2, 0);

    // ---- s1: init fc2 output = x2 + fc2_b (overlaps ln3 + fc1) ----
    cudaStreamWaitEvent(s1, evX2, 0);
    init_out<<<nInit, t256, 0, s1>>>((const float4*)p_x2, fc2_b, (float4*)out);
    cudaEventRecord(evInit, s1);

    // ---- MLP ----
    ln_kernel<<<MROWS, t256>>>(p_x2, ln3_g, ln3_b, p_ln);
    gemm_tc<<<dim3(HID / 128, MROWS / 128), t256, GSM_TOTAL>>>(
        p_ln, p_w + W_FC1, Cc, Cc, HID,
        fc1_b, nullptr, 1, nullptr, p_h1, 0);
    cudaStreamWaitEvent(0, evInit, 0);
    gemm_tc<<<dim3(Cc / 128, MROWS / 128, 2), t256, GSM_TOTAL>>>(
        p_h1, p_w + W_FC2, HID, HID / 2, Cc,
        nullptr, nullptr, 0, out, nullptr, 1);
}

// round 14
// speedup vs baseline: 1.0005x; 1.0005x over previous
#include <cuda_runtime.h>
#include <cuda_fp16.h>
#include <math.h>
#include <stdint.h>

// ---------------------------------------------------------------------------
// DinoDecoderBlock: B=8, NQ=NK=1024, C=768, H=12, HD=64, HID=3072
// Round 14: restore R11's 3-stage GEMM (R13's 4-stage regressed: loads were
// L2-resident; extra depth only cost smem/L1). Fix latent tail-wait race
// (last k-iter needs CP_WAIT(0)). Vectorized LayerNorm: 192 thr, float4 in,
// uint2 (4xfp16) out. fc2 keeps split-K=2 with red.global.add.v2.f32.
// ---------------------------------------------------------------------------

#define Bb   8
#define NQ   1024
#define NKk  1024
#define Cc   768
#define Hh   12
#define HD   64
#define HID  3072
#define MROWS (Bb*NQ)          // 8192
#define SCALE 0.125f

// ------------------------- scratch (no allocs allowed) ---------------------
__device__ float g_x1   [(size_t)MROWS*Cc];
__device__ float g_x2   [(size_t)MROWS*Cc];

__device__ __half g_qkvh [(size_t)MROWS*3*Cc];
__device__ __half g_qh   [(size_t)MROWS*Cc];
__device__ __half g_kvh  [(size_t)MROWS*2*Cc];

__device__ __half g_ln  [(size_t)MROWS*Cc];
__device__ __half g_yln [(size_t)MROWS*Cc];
__device__ __half g_ao  [(size_t)MROWS*Cc];
__device__ __half g_h1  [(size_t)MROWS*HID];

#define W_QKV   0u
#define W_APROJ 1769472u
#define W_Q     2359296u
#define W_K     2949120u
#define W_V     3538944u
#define W_CPROJ 4128768u
#define W_FC1   4718592u
#define W_FC2   7077888u
#define W_TOT   9437184u
__device__ __half g_w[W_TOT];

__device__ unsigned char g_mask[(size_t)NQ*NKk];
__device__ int g_mask_is_u8;

// --------------------------- PTX helpers -----------------------------------
__device__ __forceinline__ uint32_t smem_u32(const void* p) {
    uint32_t a;
    asm("{ .reg .u64 t; cvta.to.shared.u64 t, %1; cvt.u32.u64 %0, t; }"
        : "=r"(a) : "l"(p));
    return a;
}
__device__ __forceinline__ void cp16(uint32_t dst, const void* src) {
    asm volatile("cp.async.cg.shared.global [%0], [%1], 16;" :: "r"(dst), "l"(src));
}
#define CP_COMMIT() asm volatile("cp.async.commit_group;" ::: "memory")
#define CP_WAIT(n)  asm volatile("cp.async.wait_group %0;" :: "n"(n) : "memory")

__device__ __forceinline__ void ldm_x4(uint32_t* r, uint32_t addr) {
    asm volatile("ldmatrix.sync.aligned.m8n8.x4.shared.b16 {%0,%1,%2,%3}, [%4];"
                 : "=r"(r[0]), "=r"(r[1]), "=r"(r[2]), "=r"(r[3]) : "r"(addr));
}
__device__ __forceinline__ void ldm_x2(uint32_t* r, uint32_t addr) {
    asm volatile("ldmatrix.sync.aligned.m8n8.x2.shared.b16 {%0,%1}, [%2];"
                 : "=r"(r[0]), "=r"(r[1]) : "r"(addr));
}
__device__ __forceinline__ void ldm_x2t(uint32_t* r, uint32_t addr) {
    asm volatile("ldmatrix.sync.aligned.m8n8.x2.trans.shared.b16 {%0,%1}, [%2];"
                 : "=r"(r[0]), "=r"(r[1]) : "r"(addr));
}
__device__ __forceinline__ void mma_f16(float* d, const uint32_t* a, const uint32_t* b) {
    asm volatile(
        "mma.sync.aligned.m16n8k16.row.col.f32.f16.f16.f32 "
        "{%0,%1,%2,%3}, {%4,%5,%6,%7}, {%8,%9}, {%0,%1,%2,%3};"
        : "+f"(d[0]), "+f"(d[1]), "+f"(d[2]), "+f"(d[3])
        : "r"(a[0]), "r"(a[1]), "r"(a[2]), "r"(a[3]), "r"(b[0]), "r"(b[1]));
}
__device__ __forceinline__ uint32_t packh(float a, float b) {
    __half2 t = __floats2half2_rn(a, b);
    return *(uint32_t*)&t;
}
__device__ __forceinline__ void red2f(float* p, float v0, float v1) {
    asm volatile("red.global.add.v2.f32 [%0], {%1, %2};"
                 :: "l"(p), "f"(v0), "f"(v1) : "memory");
}

// --------------------------- weight convert --------------------------------
__global__ void wconvert_all(
    const float* __restrict__ s0, const float* __restrict__ s1,
    const float* __restrict__ s2, const float* __restrict__ s3,
    const float* __restrict__ s4, const float* __restrict__ s5,
    const float* __restrict__ s6, const float* __restrict__ s7)
{
    unsigned int i = blockIdx.x * blockDim.x + threadIdx.x;
    if (i >= W_TOT) return;
    float v;
    if      (i < W_APROJ) v = s0[i - W_QKV];
    else if (i < W_Q)     v = s1[i - W_APROJ];
    else if (i < W_K)     v = s2[i - W_Q];
    else if (i < W_V)     v = s3[i - W_K];
    else if (i < W_CPROJ) v = s4[i - W_V];
    else if (i < W_FC1)   v = s5[i - W_CPROJ];
    else if (i < W_FC2)   v = s6[i - W_FC1];
    else                  v = s7[i - W_FC2];
    g_w[i] = __float2half_rn(v);
}

// --------------------------- mask detect/decode ----------------------------
__global__ void mask_detect(const unsigned int* __restrict__ m)
{
    __shared__ int flag;
    if (threadIdx.x == 0) flag = 0;
    __syncthreads();
    for (int i = threadIdx.x; i < 65536; i += blockDim.x)
        if (m[i] > 1u) flag = 1;
    __syncthreads();
    if (threadIdx.x == 0) g_mask_is_u8 = flag;
}
__global__ void mask_decode(const void* __restrict__ msrc)
{
    size_t i = (size_t)blockIdx.x * blockDim.x + threadIdx.x;
    if (i >= (size_t)NQ * NKk) return;
    unsigned char v;
    if (g_mask_is_u8) v = ((const unsigned char*)msrc)[i] ? 1 : 0;
    else              v = ((const int*)msrc)[i] ? 1 : 0;
    g_mask[i] = v;
}

// ------------------------------ LayerNorm ----------------------------------
// 192 threads/row: one float4 load + one uint2 (4x fp16) store per thread.
__global__ void __launch_bounds__(192) ln_kernel(
    const float* __restrict__ X, const float* __restrict__ g,
    const float* __restrict__ b, __half* __restrict__ O)
{
    int row = blockIdx.x;
    const float4* x4 = (const float4*)(X + (size_t)row * Cc);
    int t = threadIdx.x;                 // 0..191
    float4 v = x4[t];
    float s  = v.x + v.y + v.z + v.w;
    float s2 = v.x*v.x + v.y*v.y + v.z*v.z + v.w*v.w;
    #pragma unroll
    for (int off = 16; off; off >>= 1) {
        s  += __shfl_xor_sync(0xffffffffu, s,  off);
        s2 += __shfl_xor_sync(0xffffffffu, s2, off);
    }
    __shared__ float shs[6], shs2[6];
    int w = t >> 5, l = t & 31;
    if (l == 0) { shs[w] = s; shs2[w] = s2; }
    __syncthreads();
    if (w == 0) {
        s  = (l < 6) ? shs[l]  : 0.f;
        s2 = (l < 6) ? shs2[l] : 0.f;
        #pragma unroll
        for (int off = 4; off; off >>= 1) {
            s  += __shfl_xor_sync(0xffffffffu, s,  off);
            s2 += __shfl_xor_sync(0xffffffffu, s2, off);
        }
        if (l == 0) { shs[0] = s; shs2[0] = s2; }
    }
    __syncthreads();
    float mean = shs[0] * (1.f / Cc);
    float var  = shs2[0] * (1.f / Cc) - mean * mean;
    float inv  = rsqrtf(var + 1e-5f);
    float4 gv = ((const float4*)g)[t];
    float4 bv = ((const float4*)b)[t];
    float o0 = (v.x - mean) * inv * gv.x + bv.x;
    float o1 = (v.y - mean) * inv * gv.y + bv.y;
    float o2 = (v.z - mean) * inv * gv.z + bv.z;
    float o3 = (v.w - mean) * inv * gv.w + bv.w;
    uint2 pk;
    pk.x = packh(o0, o1);
    pk.y = packh(o2, o3);
    ((uint2*)(O + (size_t)row * Cc))[t] = pk;
}

// ------------------ output init (for split-K accumulation) ------------------
__global__ void init_out(const float4* __restrict__ src, const float* __restrict__ bias,
                         float4* __restrict__ dst)
{
    int i = blockIdx.x * blockDim.x + threadIdx.x;
    if (i >= MROWS * Cc / 4) return;
    int c4 = (i % (Cc / 4)) * 4;
    float4 v = src[i];
    v.x += bias[c4];
    v.y += bias[c4 + 1];
    v.z += bias[c4 + 2];
    v.w += bias[c4 + 3];
    dst[i] = v;
}

// --------------------------- HMMA GEMM 128x128, 3-stage ---------------------
#define PADR 40
#define TILE_B (128 * PADR * 2)       // 10240 bytes
#define STAGE_B (2 * TILE_B)          // 20480 bytes
#define GSM_TOTAL (3 * STAGE_B)       // 61440 bytes

__global__ void __launch_bounds__(256, 2) gemm_tc(
    const __half* __restrict__ Ah, const __half* __restrict__ Bw,
    int Kstride, int Klen, int N,
    const float* __restrict__ bias, const float* __restrict__ res, int gelu,
    float* __restrict__ outF, __half* __restrict__ outH, int atomicF)
{
    extern __shared__ char smem[];
    uint32_t smb = smem_u32(smem);
    int tid = threadIdx.x;
    int wid = tid >> 5, lane = tid & 31;
    int wm = wid >> 2, wn = wid & 3;
    int m0 = blockIdx.y * 128;
    int n0 = blockIdx.x * 128;
    int kOff = blockIdx.z * Klen;

    int lr0 = tid >> 2;
    int lc  = (tid & 3) << 3;

    float acc[4][4][4];
    #pragma unroll
    for (int i = 0; i < 4; i++)
        #pragma unroll
        for (int j = 0; j < 4; j++)
            #pragma unroll
            for (int r = 0; r < 4; r++) acc[i][j][r] = 0.f;

    int NIT = Klen >> 5;

    auto load_stage = [&](int it, int s) {
        int k0 = kOff + (it << 5);
        uint32_t sb = smb + s * STAGE_B;
        #pragma unroll
        for (int tgt = 0; tgt < 2; tgt++) {
            const __half* base = (tgt == 0 ? Ah + (size_t)m0 * Kstride
                                           : Bw + (size_t)n0 * Kstride) + k0;
            uint32_t tb = sb + tgt * TILE_B;
            #pragma unroll
            for (int q = 0; q < 2; q++) {
                int row = lr0 + q * 64;
                cp16(tb + (uint32_t)(row * PADR + lc) * 2,
                     base + (size_t)row * Kstride + lc);
            }
        }
    };

    load_stage(0, 0);
    CP_COMMIT();
    load_stage(1, 1);
    CP_COMMIT();

    int s = 0;
    for (int it = 0; it < NIT; it++) {
        if (it + 1 < NIT) CP_WAIT(1);
        else              CP_WAIT(0);   // tail: only one group outstanding
        __syncthreads();
        if (it + 2 < NIT) {
            int s2 = s + 2; if (s2 >= 3) s2 -= 3;
            load_stage(it + 2, s2);
            CP_COMMIT();
        }

        uint32_t sA = smb + s * STAGE_B;
        uint32_t sB = sA + TILE_B;

        #pragma unroll
        for (int kk = 0; kk < 32; kk += 16) {
            uint32_t ah[4][4], bw[4][2];
            int arow = lane & 15;
            int acol = kk + ((lane >> 4) << 3);
            #pragma unroll
            for (int i = 0; i < 4; i++) {
                uint32_t off = (uint32_t)((wm * 64 + i * 16 + arow) * PADR + acol) * 2;
                ldm_x4(ah[i], sA + off);
            }
            int brow = lane & 7;
            int bcol = kk + ((lane >> 3) & 1) * 8;
            #pragma unroll
            for (int j = 0; j < 4; j++) {
                uint32_t off = (uint32_t)((wn * 32 + j * 8 + brow) * PADR + bcol) * 2;
                ldm_x2(bw[j], sB + off);
            }
            #pragma unroll
            for (int i = 0; i < 4; i++)
                #pragma unroll
                for (int j = 0; j < 4; j++)
                    mma_f16(acc[i][j], ah[i], bw[j]);
        }
        if (++s >= 3) s = 0;
    }

    #pragma unroll
    for (int i = 0; i < 4; i++) {
        #pragma unroll
        for (int j = 0; j < 4; j++) {
            int mb = m0 + wm * 64 + i * 16 + (lane >> 2);
            int nb = n0 + wn * 32 + j * 8 + (lane & 3) * 2;
            #pragma unroll
            for (int half = 0; half < 2; half++) {
                int m = mb + half * 8;
                float v0 = acc[i][j][half * 2 + 0];
                float v1 = acc[i][j][half * 2 + 1];
                size_t gi = (size_t)m * N + nb;
                if (atomicF) {
                    red2f(outF + gi, v0, v1);
                    continue;
                }
                if (bias) { v0 += bias[nb]; v1 += bias[nb + 1]; }
                if (gelu) {
                    v0 = 0.5f * v0 * (1.0f + erff(v0 * 0.70710678118654752f));
                    v1 = 0.5f * v1 * (1.0f + erff(v1 * 0.70710678118654752f));
                }
                if (res) {
                    float2 r2 = *(const float2*)(res + gi);
                    v0 += r2.x; v1 += r2.y;
                }
                if (outF) {
                    float2 o2 = make_float2(v0, v1);
                    *(float2*)(outF + gi) = o2;
                }
                if (outH) {
                    __half2 hh = __floats2half2_rn(v0, v1);
                    *(__half2*)(outH + gi) = hh;
                }
            }
        }
    }
}

// --------------------------- flash attention (fp16) -------------------------
#define FA_PAD 72
#define FS_Q  0u
#define FS_K  18432u
#define FS_V  36864u
#define FS_M  55296u
#define FA_SMEM 71680u

__global__ void __launch_bounds__(256, 2) flash_attn(
    const __half* __restrict__ Qsrc, const __half* __restrict__ Ksrc,
    const __half* __restrict__ Vsrc,
    size_t qBatch, size_t kvBatch, int qStride, int kvStride,
    const unsigned char* __restrict__ maskp,
    __half* __restrict__ Oh)
{
    extern __shared__ char smem[];
    uint32_t smb = smem_u32(smem);
    int tid = threadIdx.x;
    int wid = tid >> 5, lane = tid & 31;
    int wq = wid << 4;
    int bh = blockIdx.y;
    int b = bh / Hh, h = bh % Hh;
    int qrow0 = blockIdx.x * 128;

    const __half* Qb = Qsrc + (size_t)b * qBatch + h * HD;
    const __half* Kb = Ksrc + (size_t)b * kvBatch + h * HD;
    const __half* Vb = Vsrc + (size_t)b * kvBatch + h * HD;

    auto load_kv = [&](int t, int s) {
        #pragma unroll
        for (int j2 = 0; j2 < 2; j2++) {
            int idx = tid + j2 * 256;
            int r = idx >> 3, c = (idx & 7) << 3;
            cp16(smb + FS_K + s * 9216u + (uint32_t)(r * FA_PAD + c) * 2,
                 Kb + (size_t)(t * 64 + r) * kvStride + c);
            cp16(smb + FS_V + s * 9216u + (uint32_t)(r * FA_PAD + c) * 2,
                 Vb + (size_t)(t * 64 + r) * kvStride + c);
        }
        if (maskp) {
            #pragma unroll
            for (int j2 = 0; j2 < 2; j2++) {
                int idx = tid + j2 * 256;
                int r = idx >> 2, c = (idx & 3) << 4;
                cp16(smb + FS_M + s * 8192u + (uint32_t)(r * 64 + c),
                     maskp + (size_t)(qrow0 + r) * NKk + t * 64 + c);
            }
        }
    };

    #pragma unroll
    for (int j4 = 0; j4 < 4; j4++) {
        int idx = tid + j4 * 256;
        int r = idx >> 3, c = (idx & 7) << 3;
        cp16(smb + FS_Q + (uint32_t)(r * FA_PAD + c) * 2,
             Qb + (size_t)(qrow0 + r) * qStride + c);
    }
    load_kv(0, 0);
    CP_COMMIT();

    uint32_t Aq[4][4];
    float O[8][4];
    #pragma unroll
    for (int j = 0; j < 8; j++)
        #pragma unroll
        for (int e = 0; e < 4; e++) O[j][e] = 0.f;
    float m0 = -1e30f, m1 = -1e30f, l0 = 0.f, l1 = 0.f;

    int r0l = wq + (lane >> 2);
    int cb2 = (lane & 3) * 2;

    for (int t = 0; t < 16; t++) {
        int s = t & 1;
        if (t + 1 < 16) {
            load_kv(t + 1, s ^ 1);
            CP_COMMIT();
            CP_WAIT(1);
        } else {
            CP_WAIT(0);
        }
        __syncthreads();

        if (t == 0) {
            #pragma unroll
            for (int kc = 0; kc < 4; kc++) {
                uint32_t off = (uint32_t)((wq + (lane & 15)) * FA_PAD
                               + kc * 16 + ((lane >> 4) << 3)) * 2;
                ldm_x4(Aq[kc], smb + FS_Q + off);
            }
        }

        float S[8][4];
        #pragma unroll
        for (int j = 0; j < 8; j++)
            #pragma unroll
            for (int e = 0; e < 4; e++) S[j][e] = 0.f;
        uint32_t sK = smb + FS_K + s * 9216u;
        #pragma unroll
        for (int kc = 0; kc < 4; kc++) {
            #pragma unroll
            for (int j = 0; j < 8; j++) {
                uint32_t bk[2];
                uint32_t off = (uint32_t)((8 * j + (lane & 7)) * FA_PAD
                               + 16 * kc + ((lane >> 3) & 1) * 8) * 2;
                ldm_x2(bk, sK + off);
                mma_f16(S[j], Aq[kc], bk);
            }
        }

        const unsigned char* sM = (const unsigned char*)(smem + FS_M + s * 8192u);
        #pragma unroll
        for (int j = 0; j < 8; j++) {
            S[j][0] *= SCALE; S[j][1] *= SCALE;
            S[j][2] *= SCALE; S[j][3] *= SCALE;
            if (maskp) {
                int col = 8 * j + cb2;
                unsigned short mw0 = *(const unsigned short*)(sM + r0l * 64 + col);
                unsigned short mw1 = *(const unsigned short*)(sM + (r0l + 8) * 64 + col);
                if (!(mw0 & 0xFF))   S[j][0] = -1e9f;
                if (!(mw0 >> 8))     S[j][1] = -1e9f;
                if (!(mw1 & 0xFF))   S[j][2] = -1e9f;
                if (!(mw1 >> 8))     S[j][3] = -1e9f;
            }
        }

        float mx0 = -1e30f, mx1 = -1e30f;
        #pragma unroll
        for (int j = 0; j < 8; j++) {
            mx0 = fmaxf(mx0, fmaxf(S[j][0], S[j][1]));
            mx1 = fmaxf(mx1, fmaxf(S[j][2], S[j][3]));
        }
        mx0 = fmaxf(mx0, __shfl_xor_sync(0xffffffffu, mx0, 1));
        mx0 = fmaxf(mx0, __shfl_xor_sync(0xffffffffu, mx0, 2));
        mx1 = fmaxf(mx1, __shfl_xor_sync(0xffffffffu, mx1, 1));
        mx1 = fmaxf(mx1, __shfl_xor_sync(0xffffffffu, mx1, 2));
        float mn0 = fmaxf(m0, mx0), mn1 = fmaxf(m1, mx1);
        float a0 = __expf(m0 - mn0), a1 = __expf(m1 - mn1);
        float sum0 = 0.f, sum1 = 0.f;
        #pragma unroll
        for (int j = 0; j < 8; j++) {
            S[j][0] = __expf(S[j][0] - mn0); sum0 += S[j][0];
            S[j][1] = __expf(S[j][1] - mn0); sum0 += S[j][1];
            S[j][2] = __expf(S[j][2] - mn1); sum1 += S[j][2];
            S[j][3] = __expf(S[j][3] - mn1); sum1 += S[j][3];
        }
        l0 = l0 * a0 + sum0;
        l1 = l1 * a1 + sum1;
        m0 = mn0; m1 = mn1;
        #pragma unroll
        for (int j = 0; j < 8; j++) {
            O[j][0] *= a0; O[j][1] *= a0;
            O[j][2] *= a1; O[j][3] *= a1;
        }

        uint32_t sV = smb + FS_V + s * 9216u;
        #pragma unroll
        for (int kc = 0; kc < 4; kc++) {
            uint32_t Ap[4];
            Ap[0] = packh(S[2 * kc][0],     S[2 * kc][1]);
            Ap[1] = packh(S[2 * kc][2],     S[2 * kc][3]);
            Ap[2] = packh(S[2 * kc + 1][0], S[2 * kc + 1][1]);
            Ap[3] = packh(S[2 * kc + 1][2], S[2 * kc + 1][3]);
            #pragma unroll
            for (int j = 0; j < 8; j++) {
                uint32_t bv[2];
                uint32_t off = (uint32_t)((16 * kc + (lane & 15)) * FA_PAD + 8 * j) * 2;
                ldm_x2t(bv, sV + off);
                mma_f16(O[j], Ap, bv);
            }
        }
        __syncthreads();
    }

    l0 += __shfl_xor_sync(0xffffffffu, l0, 1);
    l0 += __shfl_xor_sync(0xffffffffu, l0, 2);
    l1 += __shfl_xor_sync(0xffffffffu, l1, 1);
    l1 += __shfl_xor_sync(0xffffffffu, l1, 2);
    float inv0 = 1.f / l0, inv1 = 1.f / l1;
    int grow0 = qrow0 + r0l;
    size_t obase = (size_t)b * NQ * Cc + (size_t)h * HD;
    #pragma unroll
    for (int j = 0; j < 8; j++) {
        int col = 8 * j + cb2;
        size_t gi0 = obase + (size_t)grow0 * Cc + col;
        *(__half2*)(Oh + gi0) = __floats2half2_rn(O[j][0] * inv0, O[j][1] * inv0);
        size_t gi1 = obase + (size_t)(grow0 + 8) * Cc + col;
        *(__half2*)(Oh + gi1) = __floats2half2_rn(O[j][2] * inv1, O[j][3] * inv1);
    }
}

// ------------------------------ copy (y) -----------------------------------
__global__ void copy4_kernel(const float4* __restrict__ src, float4* __restrict__ dst, int n4)
{
    int i = blockIdx.x * blockDim.x + threadIdx.x;
    if (i < n4) dst[i] = src[i];
}

// ----------------------------- launch --------------------------------------
extern "C" void kernel_launch(void* const* d_in, const int* in_sizes, int n_in,
                              void* d_out, int out_size)
{
    const float* x        = (const float*)d_in[0];
    const float* y        = (const float*)d_in[1];
    const void*  mask_raw = d_in[4];
    const float* qkv_w    = (const float*)d_in[5];
    const float* aproj_w  = (const float*)d_in[6];
    const float* aproj_b  = (const float*)d_in[7];
    const float* q_w      = (const float*)d_in[8];
    const float* k_w      = (const float*)d_in[9];
    const float* v_w      = (const float*)d_in[10];
    const float* cproj_w  = (const float*)d_in[11];
    const float* cproj_b  = (const float*)d_in[12];
    const float* fc1_w    = (const float*)d_in[13];
    const float* fc1_b    = (const float*)d_in[14];
    const float* fc2_w    = (const float*)d_in[15];
    const float* fc2_b    = (const float*)d_in[16];
    const float* ln1_g    = (const float*)d_in[17];
    const float* ln1_b    = (const float*)d_in[18];
    const float* ln2_g    = (const float*)d_in[19];
    const float* ln2_b    = (const float*)d_in[20];
    const float* ln3_g    = (const float*)d_in[21];
    const float* ln3_b    = (const float*)d_in[22];
    const float* lny_g    = (const float*)d_in[23];
    const float* lny_b    = (const float*)d_in[24];
    float* out = (float*)d_out;

    float *p_x1, *p_x2;
    __half *p_qkvh, *p_qh, *p_kvh, *p_ln, *p_yln, *p_ao, *p_h1, *p_w;
    unsigned char* p_mask;
    cudaGetSymbolAddress((void**)&p_x1,  g_x1);
    cudaGetSymbolAddress((void**)&p_x2,  g_x2);
    cudaGetSymbolAddress((void**)&p_qkvh, g_qkvh);
    cudaGetSymbolAddress((void**)&p_qh,  g_qh);
    cudaGetSymbolAddress((void**)&p_kvh, g_kvh);
    cudaGetSymbolAddress((void**)&p_ln,  g_ln);
    cudaGetSymbolAddress((void**)&p_yln, g_yln);
    cudaGetSymbolAddress((void**)&p_ao,  g_ao);
    cudaGetSymbolAddress((void**)&p_h1,  g_h1);
    cudaGetSymbolAddress((void**)&p_w,   g_w);
    cudaGetSymbolAddress((void**)&p_mask, g_mask);

    cudaFuncSetAttribute(gemm_tc, cudaFuncAttributeMaxDynamicSharedMemorySize, GSM_TOTAL);
    cudaFuncSetAttribute(flash_attn, cudaFuncAttributeMaxDynamicSharedMemorySize, FA_SMEM);

    static cudaStream_t s1 = nullptr;
    static cudaEvent_t evFork = nullptr, evW = nullptr, evKV = nullptr;
    static cudaEvent_t evX2 = nullptr, evInit = nullptr;
    if (!s1) {
        cudaStreamCreateWithFlags(&s1, cudaStreamNonBlocking);
        cudaEventCreateWithFlags(&evFork, cudaEventDisableTiming);
        cudaEventCreateWithFlags(&evW, cudaEventDisableTiming);
        cudaEventCreateWithFlags(&evKV, cudaEventDisableTiming);
        cudaEventCreateWithFlags(&evX2, cudaEventDisableTiming);
        cudaEventCreateWithFlags(&evInit, cudaEventDisableTiming);
    }

    dim3 t256(256);
    dim3 t192(192);
    dim3 gFlash(NQ / 128, Bb * Hh);
    int nInit = (MROWS * Cc / 4 + 255) / 256;

    // ---- fork ----
    cudaEventRecord(evFork, 0);
    cudaStreamWaitEvent(s1, evFork, 0);

    // ---- stream s1: weights, mask, y-branch ----
    wconvert_all<<<(W_TOT + 255) / 256, t256, 0, s1>>>(
        qkv_w, aproj_w, q_w, k_w, v_w, cproj_w, fc1_w, fc2_w);
    cudaEventRecord(evW, s1);
    mask_detect<<<1, 256, 0, s1>>>((const unsigned int*)mask_raw);
    mask_decode<<<(NQ * NKk + 255) / 256, t256, 0, s1>>>(mask_raw);
    ln_kernel<<<MROWS, t192, 0, s1>>>(y, lny_g, lny_b, p_yln);
    gemm_tc<<<dim3(2 * Cc / 128, MROWS / 128), t256, GSM_TOTAL, s1>>>(
        p_yln, p_w + W_K, Cc, Cc, 2 * Cc,
        nullptr, nullptr, 0, nullptr, p_kvh, 0);
    {
        int n4 = (MROWS * Cc) / 4;
        copy4_kernel<<<(n4 + 255) / 256, t256, 0, s1>>>((const float4*)y,
            (float4*)(out + (size_t)MROWS * Cc), n4);
    }
    cudaEventRecord(evKV, s1);

    // ---- stream 0: x-chain ----
    ln_kernel<<<MROWS, t192>>>(x, ln1_g, ln1_b, p_ln);
    cudaStreamWaitEvent(0, evW, 0);
    gemm_tc<<<dim3(3 * Cc / 128, MROWS / 128), t256, GSM_TOTAL>>>(
        p_ln, p_w + W_QKV, Cc, Cc, 3 * Cc,
        nullptr, nullptr, 0, nullptr, p_qkvh, 0);
    flash_attn<<<gFlash, t256, FA_SMEM>>>(
        p_qkvh, p_qkvh + Cc, p_qkvh + 2 * Cc,
        (size_t)NQ * 3 * Cc, (size_t)NQ * 3 * Cc, 3 * Cc, 3 * Cc,
        nullptr, p_ao);
    gemm_tc<<<dim3(Cc / 128, MROWS / 128), t256, GSM_TOTAL>>>(
        p_ao, p_w + W_APROJ, Cc, Cc, Cc,
        aproj_b, x, 0, p_x1, nullptr, 0);

    // ---- cross attention ----
    ln_kernel<<<MROWS, t192>>>(p_x1, ln2_g, ln2_b, p_ln);
    gemm_tc<<<dim3(Cc / 128, MROWS / 128), t256, GSM_TOTAL>>>(
        p_ln, p_w + W_Q, Cc, Cc, Cc,
        nullptr, nullptr, 0, nullptr, p_qh, 0);
    cudaStreamWaitEvent(0, evKV, 0);
    flash_attn<<<gFlash, t256, FA_SMEM>>>(
        p_qh, p_kvh, p_kvh + Cc,
        (size_t)NQ * Cc, (size_t)NKk * 2 * Cc, Cc, 2 * Cc,
        p_mask, p_ao);
    gemm_tc<<<dim3(Cc / 128, MROWS / 128), t256, GSM_TOTAL>>>(
        p_ao, p_w + W_CPROJ, Cc, Cc, Cc,
        cproj_b, p_x1, 0, p_x2, nullptr, 0);
    cudaEventRecord(evX2, 0);

    // ---- s1: init fc2 output = x2 + fc2_b (overlaps ln3 + fc1) ----
    cudaStreamWaitEvent(s1, evX2, 0);
    init_out<<<nInit, t256, 0, s1>>>((const float4*)p_x2, fc2_b, (float4*)out);
    cudaEventRecord(evInit, s1);

    // ---- MLP ----
    ln_kernel<<<MROWS, t192>>>(p_x2, ln3_g, ln3_b, p_ln);
    gemm_tc<<<dim3(HID / 128, MROWS / 128), t256, GSM_TOTAL>>>(
        p_ln, p_w + W_FC1, Cc, Cc, HID,
        fc1_b, nullptr, 1, nullptr, p_h1, 0);
    cudaStreamWaitEvent(0, evInit, 0);
    gemm_tc<<<dim3(Cc / 128, MROWS / 128, 2), t256, GSM_TOTAL>>>(
        p_h1, p_w + W_FC2, HID, HID / 2, Cc,
        nullptr, nullptr, 0, out, nullptr, 1);
}

// round 15
// speedup vs baseline: 1.0112x; 1.0106x over previous
#include <cuda_runtime.h>
#include <cuda_fp16.h>
#include <math.h>
#include <stdint.h>

// ---------------------------------------------------------------------------
// DinoDecoderBlock: B=8, NQ=NK=1024, C=768, H=12, HD=64, HID=3072
// Round 15: branch-free GEMM mainloop (unconditional CP_WAIT(1), final
// iteration peeled with CP_WAIT(0)). Hypothesis: R13/R14's in-loop
// conditional wait broke ptxas scheduling (-5%). Rest identical to R14.
// ---------------------------------------------------------------------------

#define Bb   8
#define NQ   1024
#define NKk  1024
#define Cc   768
#define Hh   12
#define HD   64
#define HID  3072
#define MROWS (Bb*NQ)          // 8192
#define SCALE 0.125f

// ------------------------- scratch (no allocs allowed) ---------------------
__device__ float g_x1   [(size_t)MROWS*Cc];
__device__ float g_x2   [(size_t)MROWS*Cc];

__device__ __half g_qkvh [(size_t)MROWS*3*Cc];
__device__ __half g_qh   [(size_t)MROWS*Cc];
__device__ __half g_kvh  [(size_t)MROWS*2*Cc];

__device__ __half g_ln  [(size_t)MROWS*Cc];
__device__ __half g_yln [(size_t)MROWS*Cc];
__device__ __half g_ao  [(size_t)MROWS*Cc];
__device__ __half g_h1  [(size_t)MROWS*HID];

#define W_QKV   0u
#define W_APROJ 1769472u
#define W_Q     2359296u
#define W_K     2949120u
#define W_V     3538944u
#define W_CPROJ 4128768u
#define W_FC1   4718592u
#define W_FC2   7077888u
#define W_TOT   9437184u
__device__ __half g_w[W_TOT];

__device__ unsigned char g_mask[(size_t)NQ*NKk];
__device__ int g_mask_is_u8;

// --------------------------- PTX helpers -----------------------------------
__device__ __forceinline__ uint32_t smem_u32(const void* p) {
    uint32_t a;
    asm("{ .reg .u64 t; cvta.to.shared.u64 t, %1; cvt.u32.u64 %0, t; }"
        : "=r"(a) : "l"(p));
    return a;
}
__device__ __forceinline__ void cp16(uint32_t dst, const void* src) {
    asm volatile("cp.async.cg.shared.global [%0], [%1], 16;" :: "r"(dst), "l"(src));
}
#define CP_COMMIT() asm volatile("cp.async.commit_group;" ::: "memory")
#define CP_WAIT(n)  asm volatile("cp.async.wait_group %0;" :: "n"(n) : "memory")

__device__ __forceinline__ void ldm_x4(uint32_t* r, uint32_t addr) {
    asm volatile("ldmatrix.sync.aligned.m8n8.x4.shared.b16 {%0,%1,%2,%3}, [%4];"
                 : "=r"(r[0]), "=r"(r[1]), "=r"(r[2]), "=r"(r[3]) : "r"(addr));
}
__device__ __forceinline__ void ldm_x2(uint32_t* r, uint32_t addr) {
    asm volatile("ldmatrix.sync.aligned.m8n8.x2.shared.b16 {%0,%1}, [%2];"
                 : "=r"(r[0]), "=r"(r[1]) : "r"(addr));
}
__device__ __forceinline__ void ldm_x2t(uint32_t* r, uint32_t addr) {
    asm volatile("ldmatrix.sync.aligned.m8n8.x2.trans.shared.b16 {%0,%1}, [%2];"
                 : "=r"(r[0]), "=r"(r[1]) : "r"(addr));
}
__device__ __forceinline__ void mma_f16(float* d, const uint32_t* a, const uint32_t* b) {
    asm volatile(
        "mma.sync.aligned.m16n8k16.row.col.f32.f16.f16.f32 "
        "{%0,%1,%2,%3}, {%4,%5,%6,%7}, {%8,%9}, {%0,%1,%2,%3};"
        : "+f"(d[0]), "+f"(d[1]), "+f"(d[2]), "+f"(d[3])
        : "r"(a[0]), "r"(a[1]), "r"(a[2]), "r"(a[3]), "r"(b[0]), "r"(b[1]));
}
__device__ __forceinline__ uint32_t packh(float a, float b) {
    __half2 t = __floats2half2_rn(a, b);
    return *(uint32_t*)&t;
}
__device__ __forceinline__ void red2f(float* p, float v0, float v1) {
    asm volatile("red.global.add.v2.f32 [%0], {%1, %2};"
                 :: "l"(p), "f"(v0), "f"(v1) : "memory");
}

// --------------------------- weight convert --------------------------------
__global__ void wconvert_all(
    const float* __restrict__ s0, const float* __restrict__ s1,
    const float* __restrict__ s2, const float* __restrict__ s3,
    const float* __restrict__ s4, const float* __restrict__ s5,
    const float* __restrict__ s6, const float* __restrict__ s7)
{
    unsigned int i = blockIdx.x * blockDim.x + threadIdx.x;
    if (i >= W_TOT) return;
    float v;
    if      (i < W_APROJ) v = s0[i - W_QKV];
    else if (i < W_Q)     v = s1[i - W_APROJ];
    else if (i < W_K)     v = s2[i - W_Q];
    else if (i < W_V)     v = s3[i - W_K];
    else if (i < W_CPROJ) v = s4[i - W_V];
    else if (i < W_FC1)   v = s5[i - W_CPROJ];
    else if (i < W_FC2)   v = s6[i - W_FC1];
    else                  v = s7[i - W_FC2];
    g_w[i] = __float2half_rn(v);
}

// --------------------------- mask detect/decode ----------------------------
__global__ void mask_detect(const unsigned int* __restrict__ m)
{
    __shared__ int flag;
    if (threadIdx.x == 0) flag = 0;
    __syncthreads();
    for (int i = threadIdx.x; i < 65536; i += blockDim.x)
        if (m[i] > 1u) flag = 1;
    __syncthreads();
    if (threadIdx.x == 0) g_mask_is_u8 = flag;
}
__global__ void mask_decode(const void* __restrict__ msrc)
{
    size_t i = (size_t)blockIdx.x * blockDim.x + threadIdx.x;
    if (i >= (size_t)NQ * NKk) return;
    unsigned char v;
    if (g_mask_is_u8) v = ((const unsigned char*)msrc)[i] ? 1 : 0;
    else              v = ((const int*)msrc)[i] ? 1 : 0;
    g_mask[i] = v;
}

// ------------------------------ LayerNorm ----------------------------------
__global__ void __launch_bounds__(192) ln_kernel(
    const float* __restrict__ X, const float* __restrict__ g,
    const float* __restrict__ b, __half* __restrict__ O)
{
    int row = blockIdx.x;
    const float4* x4 = (const float4*)(X + (size_t)row * Cc);
    int t = threadIdx.x;
    float4 v = x4[t];
    float s  = v.x + v.y + v.z + v.w;
    float s2 = v.x*v.x + v.y*v.y + v.z*v.z + v.w*v.w;
    #pragma unroll
    for (int off = 16; off; off >>= 1) {
        s  += __shfl_xor_sync(0xffffffffu, s,  off);
        s2 += __shfl_xor_sync(0xffffffffu, s2, off);
    }
    __shared__ float shs[6], shs2[6];
    int w = t >> 5, l = t & 31;
    if (l == 0) { shs[w] = s; shs2[w] = s2; }
    __syncthreads();
    if (w == 0) {
        s  = (l < 6) ? shs[l]  : 0.f;
        s2 = (l < 6) ? shs2[l] : 0.f;
        #pragma unroll
        for (int off = 4; off; off >>= 1) {
            s  += __shfl_xor_sync(0xffffffffu, s,  off);
            s2 += __shfl_xor_sync(0xffffffffu, s2, off);
        }
        if (l == 0) { shs[0] = s; shs2[0] = s2; }
    }
    __syncthreads();
    float mean = shs[0] * (1.f / Cc);
    float var  = shs2[0] * (1.f / Cc) - mean * mean;
    float inv  = rsqrtf(var + 1e-5f);
    float4 gv = ((const float4*)g)[t];
    float4 bv = ((const float4*)b)[t];
    float o0 = (v.x - mean) * inv * gv.x + bv.x;
    float o1 = (v.y - mean) * inv * gv.y + bv.y;
    float o2 = (v.z - mean) * inv * gv.z + bv.z;
    float o3 = (v.w - mean) * inv * gv.w + bv.w;
    uint2 pk;
    pk.x = packh(o0, o1);
    pk.y = packh(o2, o3);
    ((uint2*)(O + (size_t)row * Cc))[t] = pk;
}

// ------------------ output init (for split-K accumulation) ------------------
__global__ void init_out(const float4* __restrict__ src, const float* __restrict__ bias,
                         float4* __restrict__ dst)
{
    int i = blockIdx.x * blockDim.x + threadIdx.x;
    if (i >= MROWS * Cc / 4) return;
    int c4 = (i % (Cc / 4)) * 4;
    float4 v = src[i];
    v.x += bias[c4];
    v.y += bias[c4 + 1];
    v.z += bias[c4 + 2];
    v.w += bias[c4 + 3];
    dst[i] = v;
}

// --------------------------- HMMA GEMM 128x128, 3-stage ---------------------
#define PADR 40
#define TILE_B (128 * PADR * 2)       // 10240 bytes
#define STAGE_B (2 * TILE_B)          // 20480 bytes
#define GSM_TOTAL (3 * STAGE_B)       // 61440 bytes

__global__ void __launch_bounds__(256, 2) gemm_tc(
    const __half* __restrict__ Ah, const __half* __restrict__ Bw,
    int Kstride, int Klen, int N,
    const float* __restrict__ bias, const float* __restrict__ res, int gelu,
    float* __restrict__ outF, __half* __restrict__ outH, int atomicF)
{
    extern __shared__ char smem[];
    uint32_t smb = smem_u32(smem);
    int tid = threadIdx.x;
    int wid = tid >> 5, lane = tid & 31;
    int wm = wid >> 2, wn = wid & 3;
    int m0 = blockIdx.y * 128;
    int n0 = blockIdx.x * 128;
    int kOff = blockIdx.z * Klen;

    int lr0 = tid >> 2;
    int lc  = (tid & 3) << 3;

    float acc[4][4][4];
    #pragma unroll
    for (int i = 0; i < 4; i++)
        #pragma unroll
        for (int j = 0; j < 4; j++)
            #pragma unroll
            for (int r = 0; r < 4; r++) acc[i][j][r] = 0.f;

    int NIT = Klen >> 5;

    auto load_stage = [&](int it, int s) {
        int k0 = kOff + (it << 5);
        uint32_t sb = smb + s * STAGE_B;
        #pragma unroll
        for (int tgt = 0; tgt < 2; tgt++) {
            const __half* base = (tgt == 0 ? Ah + (size_t)m0 * Kstride
                                           : Bw + (size_t)n0 * Kstride) + k0;
            uint32_t tb = sb + tgt * TILE_B;
            #pragma unroll
            for (int q = 0; q < 2; q++) {
                int row = lr0 + q * 64;
                cp16(tb + (uint32_t)(row * PADR + lc) * 2,
                     base + (size_t)row * Kstride + lc);
            }
        }
    };

    auto compute_tile = [&](int s) {
        uint32_t sA = smb + s * STAGE_B;
        uint32_t sB = sA + TILE_B;
        #pragma unroll
        for (int kk = 0; kk < 32; kk += 16) {
            uint32_t ah[4][4], bw[4][2];
            int arow = lane & 15;
            int acol = kk + ((lane >> 4) << 3);
            #pragma unroll
            for (int i = 0; i < 4; i++) {
                uint32_t off = (uint32_t)((wm * 64 + i * 16 + arow) * PADR + acol) * 2;
                ldm_x4(ah[i], sA + off);
            }
            int brow = lane & 7;
            int bcol = kk + ((lane >> 3) & 1) * 8;
            #pragma unroll
            for (int j = 0; j < 4; j++) {
                uint32_t off = (uint32_t)((wn * 32 + j * 8 + brow) * PADR + bcol) * 2;
                ldm_x2(bw[j], sB + off);
            }
            #pragma unroll
            for (int i = 0; i < 4; i++)
                #pragma unroll
                for (int j = 0; j < 4; j++)
                    mma_f16(acc[i][j], ah[i], bw[j]);
        }
    };

    load_stage(0, 0);
    CP_COMMIT();
    load_stage(1, 1);
    CP_COMMIT();

    int s = 0;
    // main loop: unconditional WAIT(1) (fast R11 shape)
    for (int it = 0; it < NIT - 1; it++) {
        CP_WAIT(1);
        __syncthreads();
        if (it + 2 < NIT) {
            int s2 = s + 2; if (s2 >= 3) s2 -= 3;
            load_stage(it + 2, s2);
            CP_COMMIT();
        }
        compute_tile(s);
        if (++s >= 3) s = 0;
    }
    // peeled final iteration: all loads must be complete
    CP_WAIT(0);
    __syncthreads();
    compute_tile(s);

    #pragma unroll
    for (int i = 0; i < 4; i++) {
        #pragma unroll
        for (int j = 0; j < 4; j++) {
            int mb = m0 + wm * 64 + i * 16 + (lane >> 2);
            int nb = n0 + wn * 32 + j * 8 + (lane & 3) * 2;
            #pragma unroll
            for (int half = 0; half < 2; half++) {
                int m = mb + half * 8;
                float v0 = acc[i][j][half * 2 + 0];
                float v1 = acc[i][j][half * 2 + 1];
                size_t gi = (size_t)m * N + nb;
                if (atomicF) {
                    red2f(outF + gi, v0, v1);
                    continue;
                }
                if (bias) { v0 += bias[nb]; v1 += bias[nb + 1]; }
                if (gelu) {
                    v0 = 0.5f * v0 * (1.0f + erff(v0 * 0.70710678118654752f));
                    v1 = 0.5f * v1 * (1.0f + erff(v1 * 0.70710678118654752f));
                }
                if (res) {
                    float2 r2 = *(const float2*)(res + gi);
                    v0 += r2.x; v1 += r2.y;
                }
                if (outF) {
                    float2 o2 = make_float2(v0, v1);
                    *(float2*)(outF + gi) = o2;
                }
                if (outH) {
                    __half2 hh = __floats2half2_rn(v0, v1);
                    *(__half2*)(outH + gi) = hh;
                }
            }
        }
    }
}

// --------------------------- flash attention (fp16) -------------------------
#define FA_PAD 72
#define FS_Q  0u
#define FS_K  18432u
#define FS_V  36864u
#define FS_M  55296u
#define FA_SMEM 71680u

__global__ void __launch_bounds__(256, 2) flash_attn(
    const __half* __restrict__ Qsrc, const __half* __restrict__ Ksrc,
    const __half* __restrict__ Vsrc,
    size_t qBatch, size_t kvBatch, int qStride, int kvStride,
    const unsigned char* __restrict__ maskp,
    __half* __restrict__ Oh)
{
    extern __shared__ char smem[];
    uint32_t smb = smem_u32(smem);
    int tid = threadIdx.x;
    int wid = tid >> 5, lane = tid & 31;
    int wq = wid << 4;
    int bh = blockIdx.y;
    int b = bh / Hh, h = bh % Hh;
    int qrow0 = blockIdx.x * 128;

    const __half* Qb = Qsrc + (size_t)b * qBatch + h * HD;
    const __half* Kb = Ksrc + (size_t)b * kvBatch + h * HD;
    const __half* Vb = Vsrc + (size_t)b * kvBatch + h * HD;

    auto load_kv = [&](int t, int s) {
        #pragma unroll
        for (int j2 = 0; j2 < 2; j2++) {
            int idx = tid + j2 * 256;
            int r = idx >> 3, c = (idx & 7) << 3;
            cp16(smb + FS_K + s * 9216u + (uint32_t)(r * FA_PAD + c) * 2,
                 Kb + (size_t)(t * 64 + r) * kvStride + c);
            cp16(smb + FS_V + s * 9216u + (uint32_t)(r * FA_PAD + c) * 2,
                 Vb + (size_t)(t * 64 + r) * kvStride + c);
        }
        if (maskp) {
            #pragma unroll
            for (int j2 = 0; j2 < 2; j2++) {
                int idx = tid + j2 * 256;
                int r = idx >> 2, c = (idx & 3) << 4;
                cp16(smb + FS_M + s * 8192u + (uint32_t)(r * 64 + c),
                     maskp + (size_t)(qrow0 + r) * NKk + t * 64 + c);
            }
        }
    };

    #pragma unroll
    for (int j4 = 0; j4 < 4; j4++) {
        int idx = tid + j4 * 256;
        int r = idx >> 3, c = (idx & 7) << 3;
        cp16(smb + FS_Q + (uint32_t)(r * FA_PAD + c) * 2,
             Qb + (size_t)(qrow0 + r) * qStride + c);
    }
    load_kv(0, 0);
    CP_COMMIT();

    uint32_t Aq[4][4];
    float O[8][4];
    #pragma unroll
    for (int j = 0; j < 8; j++)
        #pragma unroll
        for (int e = 0; e < 4; e++) O[j][e] = 0.f;
    float m0 = -1e30f, m1 = -1e30f, l0 = 0.f, l1 = 0.f;

    int r0l = wq + (lane >> 2);
    int cb2 = (lane & 3) * 2;

    for (int t = 0; t < 16; t++) {
        int s = t & 1;
        if (t + 1 < 16) {
            load_kv(t + 1, s ^ 1);
            CP_COMMIT();
            CP_WAIT(1);
        } else {
            CP_WAIT(0);
        }
        __syncthreads();

        if (t == 0) {
            #pragma unroll
            for (int kc = 0; kc < 4; kc++) {
                uint32_t off = (uint32_t)((wq + (lane & 15)) * FA_PAD
                               + kc * 16 + ((lane >> 4) << 3)) * 2;
                ldm_x4(Aq[kc], smb + FS_Q + off);
            }
        }

        float S[8][4];
        #pragma unroll
        for (int j = 0; j < 8; j++)
            #pragma unroll
            for (int e = 0; e < 4; e++) S[j][e] = 0.f;
        uint32_t sK = smb + FS_K + s * 9216u;
        #pragma unroll
        for (int kc = 0; kc < 4; kc++) {
            #pragma unroll
            for (int j = 0; j < 8; j++) {
                uint32_t bk[2];
                uint32_t off = (uint32_t)((8 * j + (lane & 7)) * FA_PAD
                               + 16 * kc + ((lane >> 3) & 1) * 8) * 2;
                ldm_x2(bk, sK + off);
                mma_f16(S[j], Aq[kc], bk);
            }
        }

        const unsigned char* sM = (const unsigned char*)(smem + FS_M + s * 8192u);
        #pragma unroll
        for (int j = 0; j < 8; j++) {
            S[j][0] *= SCALE; S[j][1] *= SCALE;
            S[j][2] *= SCALE; S[j][3] *= SCALE;
            if (maskp) {
                int col = 8 * j + cb2;
                unsigned short mw0 = *(const unsigned short*)(sM + r0l * 64 + col);
                unsigned short mw1 = *(const unsigned short*)(sM + (r0l + 8) * 64 + col);
                if (!(mw0 & 0xFF))   S[j][0] = -1e9f;
                if (!(mw0 >> 8))     S[j][1] = -1e9f;
                if (!(mw1 & 0xFF))   S[j][2] = -1e9f;
                if (!(mw1 >> 8))     S[j][3] = -1e9f;
            }
        }

        float mx0 = -1e30f, mx1 = -1e30f;
        #pragma unroll
        for (int j = 0; j < 8; j++) {
            mx0 = fmaxf(mx0, fmaxf(S[j][0], S[j][1]));
            mx1 = fmaxf(mx1, fmaxf(S[j][2], S[j][3]));
        }
        mx0 = fmaxf(mx0, __shfl_xor_sync(0xffffffffu, mx0, 1));
        mx0 = fmaxf(mx0, __shfl_xor_sync(0xffffffffu, mx0, 2));
        mx1 = fmaxf(mx1, __shfl_xor_sync(0xffffffffu, mx1, 1));
        mx1 = fmaxf(mx1, __shfl_xor_sync(0xffffffffu, mx1, 2));
        float mn0 = fmaxf(m0, mx0), mn1 = fmaxf(m1, mx1);
        float a0 = __expf(m0 - mn0), a1 = __expf(m1 - mn1);
        float sum0 = 0.f, sum1 = 0.f;
        #pragma unroll
        for (int j = 0; j < 8; j++) {
            S[j][0] = __expf(S[j][0] - mn0); sum0 += S[j][0];
            S[j][1] = __expf(S[j][1] - mn0); sum0 += S[j][1];
            S[j][2] = __expf(S[j][2] - mn1); sum1 += S[j][2];
            S[j][3] = __expf(S[j][3] - mn1); sum1 += S[j][3];
        }
        l0 = l0 * a0 + sum0;
        l1 = l1 * a1 + sum1;
        m0 = mn0; m1 = mn1;
        #pragma unroll
        for (int j = 0; j < 8; j++) {
            O[j][0] *= a0; O[j][1] *= a0;
            O[j][2] *= a1; O[j][3] *= a1;
        }

        uint32_t sV = smb + FS_V + s * 9216u;
        #pragma unroll
        for (int kc = 0; kc < 4; kc++) {
            uint32_t Ap[4];
            Ap[0] = packh(S[2 * kc][0],     S[2 * kc][1]);
            Ap[1] = packh(S[2 * kc][2],     S[2 * kc][3]);
            Ap[2] = packh(S[2 * kc + 1][0], S[2 * kc + 1][1]);
            Ap[3] = packh(S[2 * kc + 1][2], S[2 * kc + 1][3]);
            #pragma unroll
            for (int j = 0; j < 8; j++) {
                uint32_t bv[2];
                uint32_t off = (uint32_t)((16 * kc + (lane & 15)) * FA_PAD + 8 * j) * 2;
                ldm_x2t(bv, sV + off);
                mma_f16(O[j], Ap, bv);
            }
        }
        __syncthreads();
    }

    l0 += __shfl_xor_sync(0xffffffffu, l0, 1);
    l0 += __shfl_xor_sync(0xffffffffu, l0, 2);
    l1 += __shfl_xor_sync(0xffffffffu, l1, 1);
    l1 += __shfl_xor_sync(0xffffffffu, l1, 2);
    float inv0 = 1.f / l0, inv1 = 1.f / l1;
    int grow0 = qrow0 + r0l;
    size_t obase = (size_t)b * NQ * Cc + (size_t)h * HD;
    #pragma unroll
    for (int j = 0; j < 8; j++) {
        int col = 8 * j + cb2;
        size_t gi0 = obase + (size_t)grow0 * Cc + col;
        *(__half2*)(Oh + gi0) = __floats2half2_rn(O[j][0] * inv0, O[j][1] * inv0);
        size_t gi1 = obase + (size_t)(grow0 + 8) * Cc + col;
        *(__half2*)(Oh + gi1) = __floats2half2_rn(O[j][2] * inv1, O[j][3] * inv1);
    }
}

// ------------------------------ copy (y) -----------------------------------
__global__ void copy4_kernel(const float4* __restrict__ src, float4* __restrict__ dst, int n4)
{
    int i = blockIdx.x * blockDim.x + threadIdx.x;
    if (i < n4) dst[i] = src[i];
}

// ----------------------------- launch --------------------------------------
extern "C" void kernel_launch(void* const* d_in, const int* in_sizes, int n_in,
                              void* d_out, int out_size)
{
    const float* x        = (const float*)d_in[0];
    const float* y        = (const float*)d_in[1];
    const void*  mask_raw = d_in[4];
    const float* qkv_w    = (const float*)d_in[5];
    const float* aproj_w  = (const float*)d_in[6];
    const float* aproj_b  = (const float*)d_in[7];
    const float* q_w      = (const float*)d_in[8];
    const float* k_w      = (const float*)d_in[9];
    const float* v_w      = (const float*)d_in[10];
    const float* cproj_w  = (const float*)d_in[11];
    const float* cproj_b  = (const float*)d_in[12];
    const float* fc1_w    = (const float*)d_in[13];
    const float* fc1_b    = (const float*)d_in[14];
    const float* fc2_w    = (const float*)d_in[15];
    const float* fc2_b    = (const float*)d_in[16];
    const float* ln1_g    = (const float*)d_in[17];
    const float* ln1_b    = (const float*)d_in[18];
    const float* ln2_g    = (const float*)d_in[19];
    const float* ln2_b    = (const float*)d_in[20];
    const float* ln3_g    = (const float*)d_in[21];
    const float* ln3_b    = (const float*)d_in[22];
    const float* lny_g    = (const float*)d_in[23];
    const float* lny_b    = (const float*)d_in[24];
    float* out = (float*)d_out;

    float *p_x1, *p_x2;
    __half *p_qkvh, *p_qh, *p_kvh, *p_ln, *p_yln, *p_ao, *p_h1, *p_w;
    unsigned char* p_mask;
    cudaGetSymbolAddress((void**)&p_x1,  g_x1);
    cudaGetSymbolAddress((void**)&p_x2,  g_x2);
    cudaGetSymbolAddress((void**)&p_qkvh, g_qkvh);
    cudaGetSymbolAddress((void**)&p_qh,  g_qh);
    cudaGetSymbolAddress((void**)&p_kvh, g_kvh);
    cudaGetSymbolAddress((void**)&p_ln,  g_ln);
    cudaGetSymbolAddress((void**)&p_yln, g_yln);
    cudaGetSymbolAddress((void**)&p_ao,  g_ao);
    cudaGetSymbolAddress((void**)&p_h1,  g_h1);
    cudaGetSymbolAddress((void**)&p_w,   g_w);
    cudaGetSymbolAddress((void**)&p_mask, g_mask);

    cudaFuncSetAttribute(gemm_tc, cudaFuncAttributeMaxDynamicSharedMemorySize, GSM_TOTAL);
    cudaFuncSetAttribute(flash_attn, cudaFuncAttributeMaxDynamicSharedMemorySize, FA_SMEM);

    static cudaStream_t s1 = nullptr;
    static cudaEvent_t evFork = nullptr, evW = nullptr, evKV = nullptr;
    static cudaEvent_t evX2 = nullptr, evInit = nullptr;
    if (!s1) {
        cudaStreamCreateWithFlags(&s1, cudaStreamNonBlocking);
        cudaEventCreateWithFlags(&evFork, cudaEventDisableTiming);
        cudaEventCreateWithFlags(&evW, cudaEventDisableTiming);
        cudaEventCreateWithFlags(&evKV, cudaEventDisableTiming);
        cudaEventCreateWithFlags(&evX2, cudaEventDisableTiming);
        cudaEventCreateWithFlags(&evInit, cudaEventDisableTiming);
    }

    dim3 t256(256);
    dim3 t192(192);
    dim3 gFlash(NQ / 128, Bb * Hh);
    int nInit = (MROWS * Cc / 4 + 255) / 256;

    // ---- fork ----
    cudaEventRecord(evFork, 0);
    cudaStreamWaitEvent(s1, evFork, 0);

    // ---- stream s1: weights, mask, y-branch ----
    wconvert_all<<<(W_TOT + 255) / 256, t256, 0, s1>>>(
        qkv_w, aproj_w, q_w, k_w, v_w, cproj_w, fc1_w, fc2_w);
    cudaEventRecord(evW, s1);
    mask_detect<<<1, 256, 0, s1>>>((const unsigned int*)mask_raw);
    mask_decode<<<(NQ * NKk + 255) / 256, t256, 0, s1>>>(mask_raw);
    ln_kernel<<<MROWS, t192, 0, s1>>>(y, lny_g, lny_b, p_yln);
    gemm_tc<<<dim3(2 * Cc / 128, MROWS / 128), t256, GSM_TOTAL, s1>>>(
        p_yln, p_w + W_K, Cc, Cc, 2 * Cc,
        nullptr, nullptr, 0, nullptr, p_kvh, 0);
    {
        int n4 = (MROWS * Cc) / 4;
        copy4_kernel<<<(n4 + 255) / 256, t256, 0, s1>>>((const float4*)y,
            (float4*)(out + (size_t)MROWS * Cc), n4);
    }
    cudaEventRecord(evKV, s1);

    // ---- stream 0: x-chain ----
    ln_kernel<<<MROWS, t192>>>(x, ln1_g, ln1_b, p_ln);
    cudaStreamWaitEvent(0, evW, 0);
    gemm_tc<<<dim3(3 * Cc / 128, MROWS / 128), t256, GSM_TOTAL>>>(
        p_ln, p_w + W_QKV, Cc, Cc, 3 * Cc,
        nullptr, nullptr, 0, nullptr, p_qkvh, 0);
    flash_attn<<<gFlash, t256, FA_SMEM>>>(
        p_qkvh, p_qkvh + Cc, p_qkvh + 2 * Cc,
        (size_t)NQ * 3 * Cc, (size_t)NQ * 3 * Cc, 3 * Cc, 3 * Cc,
        nullptr, p_ao);
    gemm_tc<<<dim3(Cc / 128, MROWS / 128), t256, GSM_TOTAL>>>(
        p_ao, p_w + W_APROJ, Cc, Cc, Cc,
        aproj_b, x, 0, p_x1, nullptr, 0);

    // ---- cross attention ----
    ln_kernel<<<MROWS, t192>>>(p_x1, ln2_g, ln2_b, p_ln);
    gemm_tc<<<dim3(Cc / 128, MROWS / 128), t256, GSM_TOTAL>>>(
        p_ln, p_w + W_Q, Cc, Cc, Cc,
        nullptr, nullptr, 0, nullptr, p_qh, 0);
    cudaStreamWaitEvent(0, evKV, 0);
    flash_attn<<<gFlash, t256, FA_SMEM>>>(
        p_qh, p_kvh, p_kvh + Cc,
        (size_t)NQ * Cc, (size_t)NKk * 2 * Cc, Cc, 2 * Cc,
        p_mask, p_ao);
    gemm_tc<<<dim3(Cc / 128, MROWS / 128), t256, GSM_TOTAL>>>(
        p_ao, p_w + W_CPROJ, Cc, Cc, Cc,
        cproj_b, p_x1, 0, p_x2, nullptr, 0);
    cudaEventRecord(evX2, 0);

    // ---- s1: init fc2 output = x2 + fc2_b (overlaps ln3 + fc1) ----
    cudaStreamWaitEvent(s1, evX2, 0);
    init_out<<<nInit, t256, 0, s1>>>((const float4*)p_x2, fc2_b, (float4*)out);
    cudaEventRecord(evInit, s1);

    // ---- MLP ----
    ln_kernel<<<MROWS, t192>>>(p_x2, ln3_g, ln3_b, p_ln);
    gemm_tc<<<dim3(HID / 128, MROWS / 128), t256, GSM_TOTAL>>>(
        p_ln, p_w + W_FC1, Cc, Cc, HID,
        fc1_b, nullptr, 1, nullptr, p_h1, 0);
    cudaStreamWaitEvent(0, evInit, 0);
    gemm_tc<<<dim3(Cc / 128, MROWS / 128, 2), t256, GSM_TOTAL>>>(
        p_h1, p_w + W_FC2, HID, HID / 2, Cc,
        nullptr, nullptr, 0, out, nullptr, 1);
}

// round 16
// speedup vs baseline: 1.0513x; 1.0397x over previous
#include <cuda_runtime.h>
#include <cuda_fp16.h>
#include <math.h>
#include <stdint.h>

// ---------------------------------------------------------------------------
// DinoDecoderBlock: B=8, NQ=NK=1024, C=768, H=12, HD=64, HID=3072
// Round 16: single change vs R15 — fc2 split-K partials accumulate via two
// scalar atomicAdd (R11's fast path) instead of red.global.add.v2.f32.
// Every red2f round ran >=947us; the lone scalar-atomic split-K round ran 928.
// ---------------------------------------------------------------------------

#define Bb   8
#define NQ   1024
#define NKk  1024
#define Cc   768
#define Hh   12
#define HD   64
#define HID  3072
#define MROWS (Bb*NQ)          // 8192
#define SCALE 0.125f

// ------------------------- scratch (no allocs allowed) ---------------------
__device__ float g_x1   [(size_t)MROWS*Cc];
__device__ float g_x2   [(size_t)MROWS*Cc];

__device__ __half g_qkvh [(size_t)MROWS*3*Cc];
__device__ __half g_qh   [(size_t)MROWS*Cc];
__device__ __half g_kvh  [(size_t)MROWS*2*Cc];

__device__ __half g_ln  [(size_t)MROWS*Cc];
__device__ __half g_yln [(size_t)MROWS*Cc];
__device__ __half g_ao  [(size_t)MROWS*Cc];
__device__ __half g_h1  [(size_t)MROWS*HID];

#define W_QKV   0u
#define W_APROJ 1769472u
#define W_Q     2359296u
#define W_K     2949120u
#define W_V     3538944u
#define W_CPROJ 4128768u
#define W_FC1   4718592u
#define W_FC2   7077888u
#define W_TOT   9437184u
__device__ __half g_w[W_TOT];

__device__ unsigned char g_mask[(size_t)NQ*NKk];
__device__ int g_mask_is_u8;

// --------------------------- PTX helpers -----------------------------------
__device__ __forceinline__ uint32_t smem_u32(const void* p) {
    uint32_t a;
    asm("{ .reg .u64 t; cvta.to.shared.u64 t, %1; cvt.u32.u64 %0, t; }"
        : "=r"(a) : "l"(p));
    return a;
}
__device__ __forceinline__ void cp16(uint32_t dst, const void* src) {
    asm volatile("cp.async.cg.shared.global [%0], [%1], 16;" :: "r"(dst), "l"(src));
}
#define CP_COMMIT() asm volatile("cp.async.commit_group;" ::: "memory")
#define CP_WAIT(n)  asm volatile("cp.async.wait_group %0;" :: "n"(n) : "memory")

__device__ __forceinline__ void ldm_x4(uint32_t* r, uint32_t addr) {
    asm volatile("ldmatrix.sync.aligned.m8n8.x4.shared.b16 {%0,%1,%2,%3}, [%4];"
                 : "=r"(r[0]), "=r"(r[1]), "=r"(r[2]), "=r"(r[3]) : "r"(addr));
}
__device__ __forceinline__ void ldm_x2(uint32_t* r, uint32_t addr) {
    asm volatile("ldmatrix.sync.aligned.m8n8.x2.shared.b16 {%0,%1}, [%2];"
                 : "=r"(r[0]), "=r"(r[1]) : "r"(addr));
}
__device__ __forceinline__ void ldm_x2t(uint32_t* r, uint32_t addr) {
    asm volatile("ldmatrix.sync.aligned.m8n8.x2.trans.shared.b16 {%0,%1}, [%2];"
                 : "=r"(r[0]), "=r"(r[1]) : "r"(addr));
}
__device__ __forceinline__ void mma_f16(float* d, const uint32_t* a, const uint32_t* b) {
    asm volatile(
        "mma.sync.aligned.m16n8k16.row.col.f32.f16.f16.f32 "
        "{%0,%1,%2,%3}, {%4,%5,%6,%7}, {%8,%9}, {%0,%1,%2,%3};"
        : "+f"(d[0]), "+f"(d[1]), "+f"(d[2]), "+f"(d[3])
        : "r"(a[0]), "r"(a[1]), "r"(a[2]), "r"(a[3]), "r"(b[0]), "r"(b[1]));
}
__device__ __forceinline__ uint32_t packh(float a, float b) {
    __half2 t = __floats2half2_rn(a, b);
    return *(uint32_t*)&t;
}

// --------------------------- weight convert --------------------------------
__global__ void wconvert_all(
    const float* __restrict__ s0, const float* __restrict__ s1,
    const float* __restrict__ s2, const float* __restrict__ s3,
    const float* __restrict__ s4, const float* __restrict__ s5,
    const float* __restrict__ s6, const float* __restrict__ s7)
{
    unsigned int i = blockIdx.x * blockDim.x + threadIdx.x;
    if (i >= W_TOT) return;
    float v;
    if      (i < W_APROJ) v = s0[i - W_QKV];
    else if (i < W_Q)     v = s1[i - W_APROJ];
    else if (i < W_K)     v = s2[i - W_Q];
    else if (i < W_V)     v = s3[i - W_K];
    else if (i < W_CPROJ) v = s4[i - W_V];
    else if (i < W_FC1)   v = s5[i - W_CPROJ];
    else if (i < W_FC2)   v = s6[i - W_FC1];
    else                  v = s7[i - W_FC2];
    g_w[i] = __float2half_rn(v);
}

// --------------------------- mask detect/decode ----------------------------
__global__ void mask_detect(const unsigned int* __restrict__ m)
{
    __shared__ int flag;
    if (threadIdx.x == 0) flag = 0;
    __syncthreads();
    for (int i = threadIdx.x; i < 65536; i += blockDim.x)
        if (m[i] > 1u) flag = 1;
    __syncthreads();
    if (threadIdx.x == 0) g_mask_is_u8 = flag;
}
__global__ void mask_decode(const void* __restrict__ msrc)
{
    size_t i = (size_t)blockIdx.x * blockDim.x + threadIdx.x;
    if (i >= (size_t)NQ * NKk) return;
    unsigned char v;
    if (g_mask_is_u8) v = ((const unsigned char*)msrc)[i] ? 1 : 0;
    else              v = ((const int*)msrc)[i] ? 1 : 0;
    g_mask[i] = v;
}

// ------------------------------ LayerNorm ----------------------------------
__global__ void __launch_bounds__(192) ln_kernel(
    const float* __restrict__ X, const float* __restrict__ g,
    const float* __restrict__ b, __half* __restrict__ O)
{
    int row = blockIdx.x;
    const float4* x4 = (const float4*)(X + (size_t)row * Cc);
    int t = threadIdx.x;
    float4 v = x4[t];
    float s  = v.x + v.y + v.z + v.w;
    float s2 = v.x*v.x + v.y*v.y + v.z*v.z + v.w*v.w;
    #pragma unroll
    for (int off = 16; off; off >>= 1) {
        s  += __shfl_xor_sync(0xffffffffu, s,  off);
        s2 += __shfl_xor_sync(0xffffffffu, s2, off);
    }
    __shared__ float shs[6], shs2[6];
    int w = t >> 5, l = t & 31;
    if (l == 0) { shs[w] = s; shs2[w] = s2; }
    __syncthreads();
    if (w == 0) {
        s  = (l < 6) ? shs[l]  : 0.f;
        s2 = (l < 6) ? shs2[l] : 0.f;
        #pragma unroll
        for (int off = 4; off; off >>= 1) {
            s  += __shfl_xor_sync(0xffffffffu, s,  off);
            s2 += __shfl_xor_sync(0xffffffffu, s2, off);
        }
        if (l == 0) { shs[0] = s; shs2[0] = s2; }
    }
    __syncthreads();
    float mean = shs[0] * (1.f / Cc);
    float var  = shs2[0] * (1.f / Cc) - mean * mean;
    float inv  = rsqrtf(var + 1e-5f);
    float4 gv = ((const float4*)g)[t];
    float4 bv = ((const float4*)b)[t];
    float o0 = (v.x - mean) * inv * gv.x + bv.x;
    float o1 = (v.y - mean) * inv * gv.y + bv.y;
    float o2 = (v.z - mean) * inv * gv.z + bv.z;
    float o3 = (v.w - mean) * inv * gv.w + bv.w;
    uint2 pk;
    pk.x = packh(o0, o1);
    pk.y = packh(o2, o3);
    ((uint2*)(O + (size_t)row * Cc))[t] = pk;
}

// ------------------ output init (for split-K accumulation) ------------------
__global__ void init_out(const float4* __restrict__ src, const float* __restrict__ bias,
                         float4* __restrict__ dst)
{
    int i = blockIdx.x * blockDim.x + threadIdx.x;
    if (i >= MROWS * Cc / 4) return;
    int c4 = (i % (Cc / 4)) * 4;
    float4 v = src[i];
    v.x += bias[c4];
    v.y += bias[c4 + 1];
    v.z += bias[c4 + 2];
    v.w += bias[c4 + 3];
    dst[i] = v;
}

// --------------------------- HMMA GEMM 128x128, 3-stage ---------------------
#define PADR 40
#define TILE_B (128 * PADR * 2)       // 10240 bytes
#define STAGE_B (2 * TILE_B)          // 20480 bytes
#define GSM_TOTAL (3 * STAGE_B)       // 61440 bytes

__global__ void __launch_bounds__(256, 2) gemm_tc(
    const __half* __restrict__ Ah, const __half* __restrict__ Bw,
    int Kstride, int Klen, int N,
    const float* __restrict__ bias, const float* __restrict__ res, int gelu,
    float* __restrict__ outF, __half* __restrict__ outH, int atomicF)
{
    extern __shared__ char smem[];
    uint32_t smb = smem_u32(smem);
    int tid = threadIdx.x;
    int wid = tid >> 5, lane = tid & 31;
    int wm = wid >> 2, wn = wid & 3;
    int m0 = blockIdx.y * 128;
    int n0 = blockIdx.x * 128;
    int kOff = blockIdx.z * Klen;

    int lr0 = tid >> 2;
    int lc  = (tid & 3) << 3;

    float acc[4][4][4];
    #pragma unroll
    for (int i = 0; i < 4; i++)
        #pragma unroll
        for (int j = 0; j < 4; j++)
            #pragma unroll
            for (int r = 0; r < 4; r++) acc[i][j][r] = 0.f;

    int NIT = Klen >> 5;

    auto load_stage = [&](int it, int s) {
        int k0 = kOff + (it << 5);
        uint32_t sb = smb + s * STAGE_B;
        #pragma unroll
        for (int tgt = 0; tgt < 2; tgt++) {
            const __half* base = (tgt == 0 ? Ah + (size_t)m0 * Kstride
                                           : Bw + (size_t)n0 * Kstride) + k0;
            uint32_t tb = sb + tgt * TILE_B;
            #pragma unroll
            for (int q = 0; q < 2; q++) {
                int row = lr0 + q * 64;
                cp16(tb + (uint32_t)(row * PADR + lc) * 2,
                     base + (size_t)row * Kstride + lc);
            }
        }
    };

    auto compute_tile = [&](int s) {
        uint32_t sA = smb + s * STAGE_B;
        uint32_t sB = sA + TILE_B;
        #pragma unroll
        for (int kk = 0; kk < 32; kk += 16) {
            uint32_t ah[4][4], bw[4][2];
            int arow = lane & 15;
            int acol = kk + ((lane >> 4) << 3);
            #pragma unroll
            for (int i = 0; i < 4; i++) {
                uint32_t off = (uint32_t)((wm * 64 + i * 16 + arow) * PADR + acol) * 2;
                ldm_x4(ah[i], sA + off);
            }
            int brow = lane & 7;
            int bcol = kk + ((lane >> 3) & 1) * 8;
            #pragma unroll
            for (int j = 0; j < 4; j++) {
                uint32_t off = (uint32_t)((wn * 32 + j * 8 + brow) * PADR + bcol) * 2;
                ldm_x2(bw[j], sB + off);
            }
            #pragma unroll
            for (int i = 0; i < 4; i++)
                #pragma unroll
                for (int j = 0; j < 4; j++)
                    mma_f16(acc[i][j], ah[i], bw[j]);
        }
    };

    load_stage(0, 0);
    CP_COMMIT();
    load_stage(1, 1);
    CP_COMMIT();

    int s = 0;
    for (int it = 0; it < NIT - 1; it++) {
        CP_WAIT(1);
        __syncthreads();
        if (it + 2 < NIT) {
            int s2 = s + 2; if (s2 >= 3) s2 -= 3;
            load_stage(it + 2, s2);
            CP_COMMIT();
        }
        compute_tile(s);
        if (++s >= 3) s = 0;
    }
    CP_WAIT(0);
    __syncthreads();
    compute_tile(s);

    #pragma unroll
    for (int i = 0; i < 4; i++) {
        #pragma unroll
        for (int j = 0; j < 4; j++) {
            int mb = m0 + wm * 64 + i * 16 + (lane >> 2);
            int nb = n0 + wn * 32 + j * 8 + (lane & 3) * 2;
            #pragma unroll
            for (int half = 0; half < 2; half++) {
                int m = mb + half * 8;
                float v0 = acc[i][j][half * 2 + 0];
                float v1 = acc[i][j][half * 2 + 1];
                size_t gi = (size_t)m * N + nb;
                if (atomicF) {
                    atomicAdd(outF + gi, v0);
                    atomicAdd(outF + gi + 1, v1);
                    continue;
                }
                if (bias) { v0 += bias[nb]; v1 += bias[nb + 1]; }
                if (gelu) {
                    v0 = 0.5f * v0 * (1.0f + erff(v0 * 0.70710678118654752f));
                    v1 = 0.5f * v1 * (1.0f + erff(v1 * 0.70710678118654752f));
                }
                if (res) {
                    float2 r2 = *(const float2*)(res + gi);
                    v0 += r2.x; v1 += r2.y;
                }
                if (outF) {
                    float2 o2 = make_float2(v0, v1);
                    *(float2*)(outF + gi) = o2;
                }
                if (outH) {
                    __half2 hh = __floats2half2_rn(v0, v1);
                    *(__half2*)(outH + gi) = hh;
                }
            }
        }
    }
}

// --------------------------- flash attention (fp16) -------------------------
#define FA_PAD 72
#define FS_Q  0u
#define FS_K  18432u
#define FS_V  36864u
#define FS_M  55296u
#define FA_SMEM 71680u

__global__ void __launch_bounds__(256, 2) flash_attn(
    const __half* __restrict__ Qsrc, const __half* __restrict__ Ksrc,
    const __half* __restrict__ Vsrc,
    size_t qBatch, size_t kvBatch, int qStride, int kvStride,
    const unsigned char* __restrict__ maskp,
    __half* __restrict__ Oh)
{
    extern __shared__ char smem[];
    uint32_t smb = smem_u32(smem);
    int tid = threadIdx.x;
    int wid = tid >> 5, lane = tid & 31;
    int wq = wid << 4;
    int bh = blockIdx.y;
    int b = bh / Hh, h = bh % Hh;
    int qrow0 = blockIdx.x * 128;

    const __half* Qb = Qsrc + (size_t)b * qBatch + h * HD;
    const __half* Kb = Ksrc + (size_t)b * kvBatch + h * HD;
    const __half* Vb = Vsrc + (size_t)b * kvBatch + h * HD;

    auto load_kv = [&](int t, int s) {
        #pragma unroll
        for (int j2 = 0; j2 < 2; j2++) {
            int idx = tid + j2 * 256;
            int r = idx >> 3, c = (idx & 7) << 3;
            cp16(smb + FS_K + s * 9216u + (uint32_t)(r * FA_PAD + c) * 2,
                 Kb + (size_t)(t * 64 + r) * kvStride + c);
            cp16(smb + FS_V + s * 9216u + (uint32_t)(r * FA_PAD + c) * 2,
                 Vb + (size_t)(t * 64 + r) * kvStride + c);
        }
        if (maskp) {
            #pragma unroll
            for (int j2 = 0; j2 < 2; j2++) {
                int idx = tid + j2 * 256;
                int r = idx >> 2, c = (idx & 3) << 4;
                cp16(smb + FS_M + s * 8192u + (uint32_t)(r * 64 + c),
                     maskp + (size_t)(qrow0 + r) * NKk + t * 64 + c);
            }
        }
    };

    #pragma unroll
    for (int j4 = 0; j4 < 4; j4++) {
        int idx = tid + j4 * 256;
        int r = idx >> 3, c = (idx & 7) << 3;
        cp16(smb + FS_Q + (uint32_t)(r * FA_PAD + c) * 2,
             Qb + (size_t)(qrow0 + r) * qStride + c);
    }
    load_kv(0, 0);
    CP_COMMIT();

    uint32_t Aq[4][4];
    float O[8][4];
    #pragma unroll
    for (int j = 0; j < 8; j++)
        #pragma unroll
        for (int e = 0; e < 4; e++) O[j][e] = 0.f;
    float m0 = -1e30f, m1 = -1e30f, l0 = 0.f, l1 = 0.f;

    int r0l = wq + (lane >> 2);
    int cb2 = (lane & 3) * 2;

    for (int t = 0; t < 16; t++) {
        int s = t & 1;
        if (t + 1 < 16) {
            load_kv(t + 1, s ^ 1);
            CP_COMMIT();
            CP_WAIT(1);
        } else {
            CP_WAIT(0);
        }
        __syncthreads();

        if (t == 0) {
            #pragma unroll
            for (int kc = 0; kc < 4; kc++) {
                uint32_t off = (uint32_t)((wq + (lane & 15)) * FA_PAD
                               + kc * 16 + ((lane >> 4) << 3)) * 2;
                ldm_x4(Aq[kc], smb + FS_Q + off);
            }
        }

        float S[8][4];
        #pragma unroll
        for (int j = 0; j < 8; j++)
            #pragma unroll
            for (int e = 0; e < 4; e++) S[j][e] = 0.f;
        uint32_t sK = smb + FS_K + s * 9216u;
        #pragma unroll
        for (int kc = 0; kc < 4; kc++) {
            #pragma unroll
            for (int j = 0; j < 8; j++) {
                uint32_t bk[2];
                uint32_t off = (uint32_t)((8 * j + (lane & 7)) * FA_PAD
                               + 16 * kc + ((lane >> 3) & 1) * 8) * 2;
                ldm_x2(bk, sK + off);
                mma_f16(S[j], Aq[kc], bk);
            }
        }

        const unsigned char* sM = (const unsigned char*)(smem + FS_M + s * 8192u);
        #pragma unroll
        for (int j = 0; j < 8; j++) {
            S[j][0] *= SCALE; S[j][1] *= SCALE;
            S[j][2] *= SCALE; S[j][3] *= SCALE;
            if (maskp) {
                int col = 8 * j + cb2;
                unsigned short mw0 = *(const unsigned short*)(sM + r0l * 64 + col);
                unsigned short mw1 = *(const unsigned short*)(sM + (r0l + 8) * 64 + col);
                if (!(mw0 & 0xFF))   S[j][0] = -1e9f;
                if (!(mw0 >> 8))     S[j][1] = -1e9f;
                if (!(mw1 & 0xFF))   S[j][2] = -1e9f;
                if (!(mw1 >> 8))     S[j][3] = -1e9f;
            }
        }

        float mx0 = -1e30f, mx1 = -1e30f;
        #pragma unroll
        for (int j = 0; j < 8; j++) {
            mx0 = fmaxf(mx0, fmaxf(S[j][0], S[j][1]));
            mx1 = fmaxf(mx1, fmaxf(S[j][2], S[j][3]));
        }
        mx0 = fmaxf(mx0, __shfl_xor_sync(0xffffffffu, mx0, 1));
        mx0 = fmaxf(mx0, __shfl_xor_sync(0xffffffffu, mx0, 2));
        mx1 = fmaxf(mx1, __shfl_xor_sync(0xffffffffu, mx1, 1));
        mx1 = fmaxf(mx1, __shfl_xor_sync(0xffffffffu, mx1, 2));
        float mn0 = fmaxf(m0, mx0), mn1 = fmaxf(m1, mx1);
        float a0 = __expf(m0 - mn0), a1 = __expf(m1 - mn1);
        float sum0 = 0.f, sum1 = 0.f;
        #pragma unroll
        for (int j = 0; j < 8; j++) {
            S[j][0] = __expf(S[j][0] - mn0); sum0 += S[j][0];
            S[j][1] = __expf(S[j][1] - mn0); sum0 += S[j][1];
            S[j][2] = __expf(S[j][2] - mn1); sum1 += S[j][2];
            S[j][3] = __expf(S[j][3] - mn1); sum1 += S[j][3];
        }
        l0 = l0 * a0 + sum0;
        l1 = l1 * a1 + sum1;
        m0 = mn0; m1 = mn1;
        #pragma unroll
        for (int j = 0; j < 8; j++) {
            O[j][0] *= a0; O[j][1] *= a0;
            O[j][2] *= a1; O[j][3] *= a1;
        }

        uint32_t sV = smb + FS_V + s * 9216u;
        #pragma unroll
        for (int kc = 0; kc < 4; kc++) {
            uint32_t Ap[4];
            Ap[0] = packh(S[2 * kc][0],     S[2 * kc][1]);
            Ap[1] = packh(S[2 * kc][2],     S[2 * kc][3]);
            Ap[2] = packh(S[2 * kc + 1][0], S[2 * kc + 1][1]);
            Ap[3] = packh(S[2 * kc + 1][2], S[2 * kc + 1][3]);
            #pragma unroll
            for (int j = 0; j < 8; j++) {
                uint32_t bv[2];
                uint32_t off = (uint32_t)((16 * kc + (lane & 15)) * FA_PAD + 8 * j) * 2;
                ldm_x2t(bv, sV + off);
                mma_f16(O[j], Ap, bv);
            }
        }
        __syncthreads();
    }

    l0 += __shfl_xor_sync(0xffffffffu, l0, 1);
    l0 += __shfl_xor_sync(0xffffffffu, l0, 2);
    l1 += __shfl_xor_sync(0xffffffffu, l1, 1);
    l1 += __shfl_xor_sync(0xffffffffu, l1, 2);
    float inv0 = 1.f / l0, inv1 = 1.f / l1;
    int grow0 = qrow0 + r0l;
    size_t obase = (size_t)b * NQ * Cc + (size_t)h * HD;
    #pragma unroll
    for (int j = 0; j < 8; j++) {
        int col = 8 * j + cb2;
        size_t gi0 = obase + (size_t)grow0 * Cc + col;
        *(__half2*)(Oh + gi0) = __floats2half2_rn(O[j][0] * inv0, O[j][1] * inv0);
        size_t gi1 = obase + (size_t)(grow0 + 8) * Cc + col;
        *(__half2*)(Oh + gi1) = __floats2half2_rn(O[j][2] * inv1, O[j][3] * inv1);
    }
}

// ------------------------------ copy (y) -----------------------------------
__global__ void copy4_kernel(const float4* __restrict__ src, float4* __restrict__ dst, int n4)
{
    int i = blockIdx.x * blockDim.x + threadIdx.x;
    if (i < n4) dst[i] = src[i];
}

// ----------------------------- launch --------------------------------------
extern "C" void kernel_launch(void* const* d_in, const int* in_sizes, int n_in,
                              void* d_out, int out_size)
{
    const float* x        = (const float*)d_in[0];
    const float* y        = (const float*)d_in[1];
    const void*  mask_raw = d_in[4];
    const float* qkv_w    = (const float*)d_in[5];
    const float* aproj_w  = (const float*)d_in[6];
    const float* aproj_b  = (const float*)d_in[7];
    const float* q_w      = (const float*)d_in[8];
    const float* k_w      = (const float*)d_in[9];
    const float* v_w      = (const float*)d_in[10];
    const float* cproj_w  = (const float*)d_in[11];
    const float* cproj_b  = (const float*)d_in[12];
    const float* fc1_w    = (const float*)d_in[13];
    const float* fc1_b    = (const float*)d_in[14];
    const float* fc2_w    = (const float*)d_in[15];
    const float* fc2_b    = (const float*)d_in[16];
    const float* ln1_g    = (const float*)d_in[17];
    const float* ln1_b    = (const float*)d_in[18];
    const float* ln2_g    = (const float*)d_in[19];
    const float* ln2_b    = (const float*)d_in[20];
    const float* ln3_g    = (const float*)d_in[21];
    const float* ln3_b    = (const float*)d_in[22];
    const float* lny_g    = (const float*)d_in[23];
    const float* lny_b    = (const float*)d_in[24];
    float* out = (float*)d_out;

    float *p_x1, *p_x2;
    __half *p_qkvh, *p_qh, *p_kvh, *p_ln, *p_yln, *p_ao, *p_h1, *p_w;
    unsigned char* p_mask;
    cudaGetSymbolAddress((void**)&p_x1,  g_x1);
    cudaGetSymbolAddress((void**)&p_x2,  g_x2);
    cudaGetSymbolAddress((void**)&p_qkvh, g_qkvh);
    cudaGetSymbolAddress((void**)&p_qh,  g_qh);
    cudaGetSymbolAddress((void**)&p_kvh, g_kvh);
    cudaGetSymbolAddress((void**)&p_ln,  g_ln);
    cudaGetSymbolAddress((void**)&p_yln, g_yln);
    cudaGetSymbolAddress((void**)&p_ao,  g_ao);
    cudaGetSymbolAddress((void**)&p_h1,  g_h1);
    cudaGetSymbolAddress((void**)&p_w,   g_w);
    cudaGetSymbolAddress((void**)&p_mask, g_mask);

    cudaFuncSetAttribute(gemm_tc, cudaFuncAttributeMaxDynamicSharedMemorySize, GSM_TOTAL);
    cudaFuncSetAttribute(flash_attn, cudaFuncAttributeMaxDynamicSharedMemorySize, FA_SMEM);

    static cudaStream_t s1 = nullptr;
    static cudaEvent_t evFork = nullptr, evW = nullptr, evKV = nullptr;
    static cudaEvent_t evX2 = nullptr, evInit = nullptr;
    if (!s1) {
        cudaStreamCreateWithFlags(&s1, cudaStreamNonBlocking);
        cudaEventCreateWithFlags(&evFork, cudaEventDisableTiming);
        cudaEventCreateWithFlags(&evW, cudaEventDisableTiming);
        cudaEventCreateWithFlags(&evKV, cudaEventDisableTiming);
        cudaEventCreateWithFlags(&evX2, cudaEventDisableTiming);
        cudaEventCreateWithFlags(&evInit, cudaEventDisableTiming);
    }

    dim3 t256(256);
    dim3 t192(192);
    dim3 gFlash(NQ / 128, Bb * Hh);
    int nInit = (MROWS * Cc / 4 + 255) / 256;

    // ---- fork ----
    cudaEventRecord(evFork, 0);
    cudaStreamWaitEvent(s1, evFork, 0);

    // ---- stream s1: weights, mask, y-branch ----
    wconvert_all<<<(W_TOT + 255) / 256, t256, 0, s1>>>(
        qkv_w, aproj_w, q_w, k_w, v_w, cproj_w, fc1_w, fc2_w);
    cudaEventRecord(evW, s1);
    mask_detect<<<1, 256, 0, s1>>>((const unsigned int*)mask_raw);
    mask_decode<<<(NQ * NKk + 255) / 256, t256, 0, s1>>>(mask_raw);
    ln_kernel<<<MROWS, t192, 0, s1>>>(y, lny_g, lny_b, p_yln);
    gemm_tc<<<dim3(2 * Cc / 128, MROWS / 128), t256, GSM_TOTAL, s1>>>(
        p_yln, p_w + W_K, Cc, Cc, 2 * Cc,
        nullptr, nullptr, 0, nullptr, p_kvh, 0);
    {
        int n4 = (MROWS * Cc) / 4;
        copy4_kernel<<<(n4 + 255) / 256, t256, 0, s1>>>((const float4*)y,
            (float4*)(out + (size_t)MROWS * Cc), n4);
    }
    cudaEventRecord(evKV, s1);

    // ---- stream 0: x-chain ----
    ln_kernel<<<MROWS, t192>>>(x, ln1_g, ln1_b, p_ln);
    cudaStreamWaitEvent(0, evW, 0);
    gemm_tc<<<dim3(3 * Cc / 128, MROWS / 128), t256, GSM_TOTAL>>>(
        p_ln, p_w + W_QKV, Cc, Cc, 3 * Cc,
        nullptr, nullptr, 0, nullptr, p_qkvh, 0);
    flash_attn<<<gFlash, t256, FA_SMEM>>>(
        p_qkvh, p_qkvh + Cc, p_qkvh + 2 * Cc,
        (size_t)NQ * 3 * Cc, (size_t)NQ * 3 * Cc, 3 * Cc, 3 * Cc,
        nullptr, p_ao);
    gemm_tc<<<dim3(Cc / 128, MROWS / 128), t256, GSM_TOTAL>>>(
        p_ao, p_w + W_APROJ, Cc, Cc, Cc,
        aproj_b, x, 0, p_x1, nullptr, 0);

    // ---- cross attention ----
    ln_kernel<<<MROWS, t192>>>(p_x1, ln2_g, ln2_b, p_ln);
    gemm_tc<<<dim3(Cc / 128, MROWS / 128), t256, GSM_TOTAL>>>(
        p_ln, p_w + W_Q, Cc, Cc, Cc,
        nullptr, nullptr, 0, nullptr, p_qh, 0);
    cudaStreamWaitEvent(0, evKV, 0);
    flash_attn<<<gFlash, t256, FA_SMEM>>>(
        p_qh, p_kvh, p_kvh + Cc,
        (size_t)NQ * Cc, (size_t)NKk * 2 * Cc, Cc, 2 * Cc,
        p_mask, p_ao);
    gemm_tc<<<dim3(Cc / 128, MROWS / 128), t256, GSM_TOTAL>>>(
        p_ao, p_w + W_CPROJ, Cc, Cc, Cc,
        cproj_b, p_x1, 0, p_x2, nullptr, 0);
    cudaEventRecord(evX2, 0);

    // ---- s1: init fc2 output = x2 + fc2_b (overlaps ln3 + fc1) ----
    cudaStreamWaitEvent(s1, evX2, 0);
    init_out<<<nInit, t256, 0, s1>>>((const float4*)p_x2, fc2_b, (float4*)out);
    cudaEventRecord(evInit, s1);

    // ---- MLP ----
    ln_kernel<<<MROWS, t192>>>(p_x2, ln3_g, ln3_b, p_ln);
    gemm_tc<<<dim3(HID / 128, MROWS / 128), t256, GSM_TOTAL>>>(
        p_ln, p_w + W_FC1, Cc, Cc, HID,
        fc1_b, nullptr, 1, nullptr, p_h1, 0);
    cudaStreamWaitEvent(0, evInit, 0);
    gemm_tc<<<dim3(Cc / 128, MROWS / 128, 2), t256, GSM_TOTAL>>>(
        p_h1, p_w + W_FC2, HID, HID / 2, Cc,
        nullptr, nullptr, 0, out, nullptr, 1);
}

// round 17
// speedup vs baseline: 1.1206x; 1.0659x over previous
#include <cuda_runtime.h>
#include <cuda_fp16.h>
#include <math.h>
#include <stdint.h>

// ---------------------------------------------------------------------------
// DinoDecoderBlock: B=8, NQ=NK=1024, C=768, H=12, HD=64, HID=3072
// Round 17: R16 base (best, 927.8us) + ldmatrix.x4 batching: flash K loads,
// flash V trans loads, and GEMM B loads each fetch 2 j-tiles per instruction
// (address lanes pick the tile; data distribution is standard). Halves the
// ldmatrix issue count in the issue-balanced flash kernel.
// ---------------------------------------------------------------------------

#define Bb   8
#define NQ   1024
#define NKk  1024
#define Cc   768
#define Hh   12
#define HD   64
#define HID  3072
#define MROWS (Bb*NQ)          // 8192
#define SCALE 0.125f

// ------------------------- scratch (no allocs allowed) ---------------------
__device__ float g_x1   [(size_t)MROWS*Cc];
__device__ float g_x2   [(size_t)MROWS*Cc];

__device__ __half g_qkvh [(size_t)MROWS*3*Cc];
__device__ __half g_qh   [(size_t)MROWS*Cc];
__device__ __half g_kvh  [(size_t)MROWS*2*Cc];

__device__ __half g_ln  [(size_t)MROWS*Cc];
__device__ __half g_yln [(size_t)MROWS*Cc];
__device__ __half g_ao  [(size_t)MROWS*Cc];
__device__ __half g_h1  [(size_t)MROWS*HID];

#define W_QKV   0u
#define W_APROJ 1769472u
#define W_Q     2359296u
#define W_K     2949120u
#define W_V     3538944u
#define W_CPROJ 4128768u
#define W_FC1   4718592u
#define W_FC2   7077888u
#define W_TOT   9437184u
__device__ __half g_w[W_TOT];

__device__ unsigned char g_mask[(size_t)NQ*NKk];
__device__ int g_mask_is_u8;

// --------------------------- PTX helpers -----------------------------------
__device__ __forceinline__ uint32_t smem_u32(const void* p) {
    uint32_t a;
    asm("{ .reg .u64 t; cvta.to.shared.u64 t, %1; cvt.u32.u64 %0, t; }"
        : "=r"(a) : "l"(p));
    return a;
}
__device__ __forceinline__ void cp16(uint32_t dst, const void* src) {
    asm volatile("cp.async.cg.shared.global [%0], [%1], 16;" :: "r"(dst), "l"(src));
}
#define CP_COMMIT() asm volatile("cp.async.commit_group;" ::: "memory")
#define CP_WAIT(n)  asm volatile("cp.async.wait_group %0;" :: "n"(n) : "memory")

__device__ __forceinline__ void ldm_x4(uint32_t* r, uint32_t addr) {
    asm volatile("ldmatrix.sync.aligned.m8n8.x4.shared.b16 {%0,%1,%2,%3}, [%4];"
                 : "=r"(r[0]), "=r"(r[1]), "=r"(r[2]), "=r"(r[3]) : "r"(addr));
}
__device__ __forceinline__ void ldm_x4t(uint32_t* r, uint32_t addr) {
    asm volatile("ldmatrix.sync.aligned.m8n8.x4.trans.shared.b16 {%0,%1,%2,%3}, [%4];"
                 : "=r"(r[0]), "=r"(r[1]), "=r"(r[2]), "=r"(r[3]) : "r"(addr));
}
__device__ __forceinline__ void mma_f16(float* d, const uint32_t* a, const uint32_t* b) {
    asm volatile(
        "mma.sync.aligned.m16n8k16.row.col.f32.f16.f16.f32 "
        "{%0,%1,%2,%3}, {%4,%5,%6,%7}, {%8,%9}, {%0,%1,%2,%3};"
        : "+f"(d[0]), "+f"(d[1]), "+f"(d[2]), "+f"(d[3])
        : "r"(a[0]), "r"(a[1]), "r"(a[2]), "r"(a[3]), "r"(b[0]), "r"(b[1]));
}
__device__ __forceinline__ uint32_t packh(float a, float b) {
    __half2 t = __floats2half2_rn(a, b);
    return *(uint32_t*)&t;
}

// --------------------------- weight convert --------------------------------
__global__ void wconvert_all(
    const float* __restrict__ s0, const float* __restrict__ s1,
    const float* __restrict__ s2, const float* __restrict__ s3,
    const float* __restrict__ s4, const float* __restrict__ s5,
    const float* __restrict__ s6, const float* __restrict__ s7)
{
    unsigned int i = blockIdx.x * blockDim.x + threadIdx.x;
    if (i >= W_TOT) return;
    float v;
    if      (i < W_APROJ) v = s0[i - W_QKV];
    else if (i < W_Q)     v = s1[i - W_APROJ];
    else if (i < W_K)     v = s2[i - W_Q];
    else if (i < W_V)     v = s3[i - W_K];
    else if (i < W_CPROJ) v = s4[i - W_V];
    else if (i < W_FC1)   v = s5[i - W_CPROJ];
    else if (i < W_FC2)   v = s6[i - W_FC1];
    else                  v = s7[i - W_FC2];
    g_w[i] = __float2half_rn(v);
}

// --------------------------- mask detect/decode ----------------------------
__global__ void mask_detect(const unsigned int* __restrict__ m)
{
    __shared__ int flag;
    if (threadIdx.x == 0) flag = 0;
    __syncthreads();
    for (int i = threadIdx.x; i < 65536; i += blockDim.x)
        if (m[i] > 1u) flag = 1;
    __syncthreads();
    if (threadIdx.x == 0) g_mask_is_u8 = flag;
}
__global__ void mask_decode(const void* __restrict__ msrc)
{
    size_t i = (size_t)blockIdx.x * blockDim.x + threadIdx.x;
    if (i >= (size_t)NQ * NKk) return;
    unsigned char v;
    if (g_mask_is_u8) v = ((const unsigned char*)msrc)[i] ? 1 : 0;
    else              v = ((const int*)msrc)[i] ? 1 : 0;
    g_mask[i] = v;
}

// ------------------------------ LayerNorm ----------------------------------
__global__ void __launch_bounds__(192) ln_kernel(
    const float* __restrict__ X, const float* __restrict__ g,
    const float* __restrict__ b, __half* __restrict__ O)
{
    int row = blockIdx.x;
    const float4* x4 = (const float4*)(X + (size_t)row * Cc);
    int t = threadIdx.x;
    float4 v = x4[t];
    float s  = v.x + v.y + v.z + v.w;
    float s2 = v.x*v.x + v.y*v.y + v.z*v.z + v.w*v.w;
    #pragma unroll
    for (int off = 16; off; off >>= 1) {
        s  += __shfl_xor_sync(0xffffffffu, s,  off);
        s2 += __shfl_xor_sync(0xffffffffu, s2, off);
    }
    __shared__ float shs[6], shs2[6];
    int w = t >> 5, l = t & 31;
    if (l == 0) { shs[w] = s; shs2[w] = s2; }
    __syncthreads();
    if (w == 0) {
        s  = (l < 6) ? shs[l]  : 0.f;
        s2 = (l < 6) ? shs2[l] : 0.f;
        #pragma unroll
        for (int off = 4; off; off >>= 1) {
            s  += __shfl_xor_sync(0xffffffffu, s,  off);
            s2 += __shfl_xor_sync(0xffffffffu, s2, off);
        }
        if (l == 0) { shs[0] = s; shs2[0] = s2; }
    }
    __syncthreads();
    float mean = shs[0] * (1.f / Cc);
    float var  = shs2[0] * (1.f / Cc) - mean * mean;
    float inv  = rsqrtf(var + 1e-5f);
    float4 gv = ((const float4*)g)[t];
    float4 bv = ((const float4*)b)[t];
    float o0 = (v.x - mean) * inv * gv.x + bv.x;
    float o1 = (v.y - mean) * inv * gv.y + bv.y;
    float o2 = (v.z - mean) * inv * gv.z + bv.z;
    float o3 = (v.w - mean) * inv * gv.w + bv.w;
    uint2 pk;
    pk.x = packh(o0, o1);
    pk.y = packh(o2, o3);
    ((uint2*)(O + (size_t)row * Cc))[t] = pk;
}

// ------------------ output init (for split-K accumulation) ------------------
__global__ void init_out(const float4* __restrict__ src, const float* __restrict__ bias,
                         float4* __restrict__ dst)
{
    int i = blockIdx.x * blockDim.x + threadIdx.x;
    if (i >= MROWS * Cc / 4) return;
    int c4 = (i % (Cc / 4)) * 4;
    float4 v = src[i];
    v.x += bias[c4];
    v.y += bias[c4 + 1];
    v.z += bias[c4 + 2];
    v.w += bias[c4 + 3];
    dst[i] = v;
}

// --------------------------- HMMA GEMM 128x128, 3-stage ---------------------
#define PADR 40
#define TILE_B (128 * PADR * 2)       // 10240 bytes
#define STAGE_B (2 * TILE_B)          // 20480 bytes
#define GSM_TOTAL (3 * STAGE_B)       // 61440 bytes

__global__ void __launch_bounds__(256, 2) gemm_tc(
    const __half* __restrict__ Ah, const __half* __restrict__ Bw,
    int Kstride, int Klen, int N,
    const float* __restrict__ bias, const float* __restrict__ res, int gelu,
    float* __restrict__ outF, __half* __restrict__ outH, int atomicF)
{
    extern __shared__ char smem[];
    uint32_t smb = smem_u32(smem);
    int tid = threadIdx.x;
    int wid = tid >> 5, lane = tid & 31;
    int wm = wid >> 2, wn = wid & 3;
    int m0 = blockIdx.y * 128;
    int n0 = blockIdx.x * 128;
    int kOff = blockIdx.z * Klen;

    int lr0 = tid >> 2;
    int lc  = (tid & 3) << 3;
    int l8   = lane & 7;
    int pair = (lane >> 3) & 1;     // k-half selector for B x4
    int duo  = lane >> 4;           // j selector within pair for B x4

    float acc[4][4][4];
    #pragma unroll
    for (int i = 0; i < 4; i++)
        #pragma unroll
        for (int j = 0; j < 4; j++)
            #pragma unroll
            for (int r = 0; r < 4; r++) acc[i][j][r] = 0.f;

    int NIT = Klen >> 5;

    auto load_stage = [&](int it, int s) {
        int k0 = kOff + (it << 5);
        uint32_t sb = smb + s * STAGE_B;
        #pragma unroll
        for (int tgt = 0; tgt < 2; tgt++) {
            const __half* base = (tgt == 0 ? Ah + (size_t)m0 * Kstride
                                           : Bw + (size_t)n0 * Kstride) + k0;
            uint32_t tb = sb + tgt * TILE_B;
            #pragma unroll
            for (int q = 0; q < 2; q++) {
                int row = lr0 + q * 64;
                cp16(tb + (uint32_t)(row * PADR + lc) * 2,
                     base + (size_t)row * Kstride + lc);
            }
        }
    };

    auto compute_tile = [&](int s) {
        uint32_t sA = smb + s * STAGE_B;
        uint32_t sB = sA + TILE_B;
        #pragma unroll
        for (int kk = 0; kk < 32; kk += 16) {
            uint32_t ah[4][4], bw[4][2];
            int arow = lane & 15;
            int acol = kk + ((lane >> 4) << 3);
            #pragma unroll
            for (int i = 0; i < 4; i++) {
                uint32_t off = (uint32_t)((wm * 64 + i * 16 + arow) * PADR + acol) * 2;
                ldm_x4(ah[i], sA + off);
            }
            // B: two j-tiles per x4 (m0/m1 = jb k-lo/hi, m2/m3 = jb+1 k-lo/hi)
            #pragma unroll
            for (int jb = 0; jb < 4; jb += 2) {
                uint32_t r4[4];
                uint32_t off = (uint32_t)((wn * 32 + (jb + duo) * 8 + l8) * PADR
                               + kk + pair * 8) * 2;
                ldm_x4(r4, sB + off);
                bw[jb][0] = r4[0];     bw[jb][1] = r4[1];
                bw[jb + 1][0] = r4[2]; bw[jb + 1][1] = r4[3];
            }
            #pragma unroll
            for (int i = 0; i < 4; i++)
                #pragma unroll
                for (int j = 0; j < 4; j++)
                    mma_f16(acc[i][j], ah[i], bw[j]);
        }
    };

    load_stage(0, 0);
    CP_COMMIT();
    load_stage(1, 1);
    CP_COMMIT();

    int s = 0;
    for (int it = 0; it < NIT - 1; it++) {
        CP_WAIT(1);
        __syncthreads();
        if (it + 2 < NIT) {
            int s2 = s + 2; if (s2 >= 3) s2 -= 3;
            load_stage(it + 2, s2);
            CP_COMMIT();
        }
        compute_tile(s);
        if (++s >= 3) s = 0;
    }
    CP_WAIT(0);
    __syncthreads();
    compute_tile(s);

    #pragma unroll
    for (int i = 0; i < 4; i++) {
        #pragma unroll
        for (int j = 0; j < 4; j++) {
            int mb = m0 + wm * 64 + i * 16 + (lane >> 2);
            int nb = n0 + wn * 32 + j * 8 + (lane & 3) * 2;
            #pragma unroll
            for (int half = 0; half < 2; half++) {
                int m = mb + half * 8;
                float v0 = acc[i][j][half * 2 + 0];
                float v1 = acc[i][j][half * 2 + 1];
                size_t gi = (size_t)m * N + nb;
                if (atomicF) {
                    atomicAdd(outF + gi, v0);
                    atomicAdd(outF + gi + 1, v1);
                    continue;
                }
                if (bias) { v0 += bias[nb]; v1 += bias[nb + 1]; }
                if (gelu) {
                    v0 = 0.5f * v0 * (1.0f + erff(v0 * 0.70710678118654752f));
                    v1 = 0.5f * v1 * (1.0f + erff(v1 * 0.70710678118654752f));
                }
                if (res) {
                    float2 r2 = *(const float2*)(res + gi);
                    v0 += r2.x; v1 += r2.y;
                }
                if (outF) {
                    float2 o2 = make_float2(v0, v1);
                    *(float2*)(outF + gi) = o2;
                }
                if (outH) {
                    __half2 hh = __floats2half2_rn(v0, v1);
                    *(__half2*)(outH + gi) = hh;
                }
            }
        }
    }
}

// --------------------------- flash attention (fp16) -------------------------
#define FA_PAD 72
#define FS_Q  0u
#define FS_K  18432u
#define FS_V  36864u
#define FS_M  55296u
#define FA_SMEM 71680u

__global__ void __launch_bounds__(256, 2) flash_attn(
    const __half* __restrict__ Qsrc, const __half* __restrict__ Ksrc,
    const __half* __restrict__ Vsrc,
    size_t qBatch, size_t kvBatch, int qStride, int kvStride,
    const unsigned char* __restrict__ maskp,
    __half* __restrict__ Oh)
{
    extern __shared__ char smem[];
    uint32_t smb = smem_u32(smem);
    int tid = threadIdx.x;
    int wid = tid >> 5, lane = tid & 31;
    int wq = wid << 4;
    int bh = blockIdx.y;
    int b = bh / Hh, h = bh % Hh;
    int qrow0 = blockIdx.x * 128;

    int l8   = lane & 7;
    int pair = (lane >> 3) & 1;
    int duo  = lane >> 4;

    const __half* Qb = Qsrc + (size_t)b * qBatch + h * HD;
    const __half* Kb = Ksrc + (size_t)b * kvBatch + h * HD;
    const __half* Vb = Vsrc + (size_t)b * kvBatch + h * HD;

    auto load_kv = [&](int t, int s) {
        #pragma unroll
        for (int j2 = 0; j2 < 2; j2++) {
            int idx = tid + j2 * 256;
            int r = idx >> 3, c = (idx & 7) << 3;
            cp16(smb + FS_K + s * 9216u + (uint32_t)(r * FA_PAD + c) * 2,
                 Kb + (size_t)(t * 64 + r) * kvStride + c);
            cp16(smb + FS_V + s * 9216u + (uint32_t)(r * FA_PAD + c) * 2,
                 Vb + (size_t)(t * 64 + r) * kvStride + c);
        }
        if (maskp) {
            #pragma unroll
            for (int j2 = 0; j2 < 2; j2++) {
                int idx = tid + j2 * 256;
                int r = idx >> 2, c = (idx & 3) << 4;
                cp16(smb + FS_M + s * 8192u + (uint32_t)(r * 64 + c),
                     maskp + (size_t)(qrow0 + r) * NKk + t * 64 + c);
            }
        }
    };

    #pragma unroll
    for (int j4 = 0; j4 < 4; j4++) {
        int idx = tid + j4 * 256;
        int r = idx >> 3, c = (idx & 7) << 3;
        cp16(smb + FS_Q + (uint32_t)(r * FA_PAD + c) * 2,
             Qb + (size_t)(qrow0 + r) * qStride + c);
    }
    load_kv(0, 0);
    CP_COMMIT();

    uint32_t Aq[4][4];
    float O[8][4];
    #pragma unroll
    for (int j = 0; j < 8; j++)
        #pragma unroll
        for (int e = 0; e < 4; e++) O[j][e] = 0.f;
    float m0 = -1e30f, m1 = -1e30f, l0 = 0.f, l1 = 0.f;

    int r0l = wq + (lane >> 2);
    int cb2 = (lane & 3) * 2;

    for (int t = 0; t < 16; t++) {
        int s = t & 1;
        if (t + 1 < 16) {
            load_kv(t + 1, s ^ 1);
            CP_COMMIT();
            CP_WAIT(1);
        } else {
            CP_WAIT(0);
        }
        __syncthreads();

        if (t == 0) {
            #pragma unroll
            for (int kc = 0; kc < 4; kc++) {
                uint32_t off = (uint32_t)((wq + (lane & 15)) * FA_PAD
                               + kc * 16 + ((lane >> 4) << 3)) * 2;
                ldm_x4(Aq[kc], smb + FS_Q + off);
            }
        }

        // ---- S = Q @ K^T ----  (K loads: 2 j-tiles per x4)
        float S[8][4];
        #pragma unroll
        for (int j = 0; j < 8; j++)
            #pragma unroll
            for (int e = 0; e < 4; e++) S[j][e] = 0.f;
        uint32_t sK = smb + FS_K + s * 9216u;
        #pragma unroll
        for (int kc = 0; kc < 4; kc++) {
            #pragma unroll
            for (int jb = 0; jb < 8; jb += 2) {
                uint32_t r4[4];
                uint32_t off = (uint32_t)(((jb + duo) * 8 + l8) * FA_PAD
                               + 16 * kc + pair * 8) * 2;
                ldm_x4(r4, sK + off);
                mma_f16(S[jb],     Aq[kc], r4);
                mma_f16(S[jb + 1], Aq[kc], r4 + 2);
            }
        }

        const unsigned char* sM = (const unsigned char*)(smem + FS_M + s * 8192u);
        #pragma unroll
        for (int j = 0; j < 8; j++) {
            S[j][0] *= SCALE; S[j][1] *= SCALE;
            S[j][2] *= SCALE; S[j][3] *= SCALE;
            if (maskp) {
                int col = 8 * j + cb2;
                unsigned short mw0 = *(const unsigned short*)(sM + r0l * 64 + col);
                unsigned short mw1 = *(const unsigned short*)(sM + (r0l + 8) * 64 + col);
                if (!(mw0 & 0xFF))   S[j][0] = -1e9f;
                if (!(mw0 >> 8))     S[j][1] = -1e9f;
                if (!(mw1 & 0xFF))   S[j][2] = -1e9f;
                if (!(mw1 >> 8))     S[j][3] = -1e9f;
            }
        }

        float mx0 = -1e30f, mx1 = -1e30f;
        #pragma unroll
        for (int j = 0; j < 8; j++) {
            mx0 = fmaxf(mx0, fmaxf(S[j][0], S[j][1]));
            mx1 = fmaxf(mx1, fmaxf(S[j][2], S[j][3]));
        }
        mx0 = fmaxf(mx0, __shfl_xor_sync(0xffffffffu, mx0, 1));
        mx0 = fmaxf(mx0, __shfl_xor_sync(0xffffffffu, mx0, 2));
        mx1 = fmaxf(mx1, __shfl_xor_sync(0xffffffffu, mx1, 1));
        mx1 = fmaxf(mx1, __shfl_xor_sync(0xffffffffu, mx1, 2));
        float mn0 = fmaxf(m0, mx0), mn1 = fmaxf(m1, mx1);
        float a0 = __expf(m0 - mn0), a1 = __expf(m1 - mn1);
        float sum0 = 0.f, sum1 = 0.f;
        #pragma unroll
        for (int j = 0; j < 8; j++) {
            S[j][0] = __expf(S[j][0] - mn0); sum0 += S[j][0];
            S[j][1] = __expf(S[j][1] - mn0); sum0 += S[j][1];
            S[j][2] = __expf(S[j][2] - mn1); sum1 += S[j][2];
            S[j][3] = __expf(S[j][3] - mn1); sum1 += S[j][3];
        }
        l0 = l0 * a0 + sum0;
        l1 = l1 * a1 + sum1;
        m0 = mn0; m1 = mn1;
        #pragma unroll
        for (int j = 0; j < 8; j++) {
            O[j][0] *= a0; O[j][1] *= a0;
            O[j][2] *= a1; O[j][3] *= a1;
        }

        // ---- O += P @ V ----  (V trans loads: 2 j-tiles per x4.trans)
        uint32_t sV = smb + FS_V + s * 9216u;
        #pragma unroll
        for (int kc = 0; kc < 4; kc++) {
            uint32_t Ap[4];
            Ap[0] = packh(S[2 * kc][0],     S[2 * kc][1]);
            Ap[1] = packh(S[2 * kc][2],     S[2 * kc][3]);
            Ap[2] = packh(S[2 * kc + 1][0], S[2 * kc + 1][1]);
            Ap[3] = packh(S[2 * kc + 1][2], S[2 * kc + 1][3]);
            #pragma unroll
            for (int jb = 0; jb < 8; jb += 2) {
                uint32_t r4[4];
                uint32_t off = (uint32_t)((16 * kc + pair * 8 + l8) * FA_PAD
                               + 8 * (jb + duo)) * 2;
                ldm_x4t(r4, sV + off);
                mma_f16(O[jb],     Ap, r4);
                mma_f16(O[jb + 1], Ap, r4 + 2);
            }
        }
        __syncthreads();
    }

    l0 += __shfl_xor_sync(0xffffffffu, l0, 1);
    l0 += __shfl_xor_sync(0xffffffffu, l0, 2);
    l1 += __shfl_xor_sync(0xffffffffu, l1, 1);
    l1 += __shfl_xor_sync(0xffffffffu, l1, 2);
    float inv0 = 1.f / l0, inv1 = 1.f / l1;
    int grow0 = qrow0 + r0l;
    size_t obase = (size_t)b * NQ * Cc + (size_t)h * HD;
    #pragma unroll
    for (int j = 0; j < 8; j++) {
        int col = 8 * j + cb2;
        size_t gi0 = obase + (size_t)grow0 * Cc + col;
        *(__half2*)(Oh + gi0) = __floats2half2_rn(O[j][0] * inv0, O[j][1] * inv0);
        size_t gi1 = obase + (size_t)(grow0 + 8) * Cc + col;
        *(__half2*)(Oh + gi1) = __floats2half2_rn(O[j][2] * inv1, O[j][3] * inv1);
    }
}

// ------------------------------ copy (y) -----------------------------------
__global__ void copy4_kernel(const float4* __restrict__ src, float4* __restrict__ dst, int n4)
{
    int i = blockIdx.x * blockDim.x + threadIdx.x;
    if (i < n4) dst[i] = src[i];
}

// ----------------------------- launch --------------------------------------
extern "C" void kernel_launch(void* const* d_in, const int* in_sizes, int n_in,
                              void* d_out, int out_size)
{
    const float* x        = (const float*)d_in[0];
    const float* y        = (const float*)d_in[1];
    const void*  mask_raw = d_in[4];
    const float* qkv_w    = (const float*)d_in[5];
    const float* aproj_w  = (const float*)d_in[6];
    const float* aproj_b  = (const float*)d_in[7];
    const float* q_w      = (const float*)d_in[8];
    const float* k_w      = (const float*)d_in[9];
    const float* v_w      = (const float*)d_in[10];
    const float* cproj_w  = (const float*)d_in[11];
    const float* cproj_b  = (const float*)d_in[12];
    const float* fc1_w    = (const float*)d_in[13];
    const float* fc1_b    = (const float*)d_in[14];
    const float* fc2_w    = (const float*)d_in[15];
    const float* fc2_b    = (const float*)d_in[16];
    const float* ln1_g    = (const float*)d_in[17];
    const float* ln1_b    = (const float*)d_in[18];
    const float* ln2_g    = (const float*)d_in[19];
    const float* ln2_b    = (const float*)d_in[20];
    const float* ln3_g    = (const float*)d_in[21];
    const float* ln3_b    = (const float*)d_in[22];
    const float* lny_g    = (const float*)d_in[23];
    const float* lny_b    = (const float*)d_in[24];
    float* out = (float*)d_out;

    float *p_x1, *p_x2;
    __half *p_qkvh, *p_qh, *p_kvh, *p_ln, *p_yln, *p_ao, *p_h1, *p_w;
    unsigned char* p_mask;
    cudaGetSymbolAddress((void**)&p_x1,  g_x1);
    cudaGetSymbolAddress((void**)&p_x2,  g_x2);
    cudaGetSymbolAddress((void**)&p_qkvh, g_qkvh);
    cudaGetSymbolAddress((void**)&p_qh,  g_qh);
    cudaGetSymbolAddress((void**)&p_kvh, g_kvh);
    cudaGetSymbolAddress((void**)&p_ln,  g_ln);
    cudaGetSymbolAddress((void**)&p_yln, g_yln);
    cudaGetSymbolAddress((void**)&p_ao,  g_ao);
    cudaGetSymbolAddress((void**)&p_h1,  g_h1);
    cudaGetSymbolAddress((void**)&p_w,   g_w);
    cudaGetSymbolAddress((void**)&p_mask, g_mask);

    cudaFuncSetAttribute(gemm_tc, cudaFuncAttributeMaxDynamicSharedMemorySize, GSM_TOTAL);
    cudaFuncSetAttribute(flash_attn, cudaFuncAttributeMaxDynamicSharedMemorySize, FA_SMEM);

    static cudaStream_t s1 = nullptr;
    static cudaEvent_t evFork = nullptr, evW = nullptr, evKV = nullptr;
    static cudaEvent_t evX2 = nullptr, evInit = nullptr;
    if (!s1) {
        cudaStreamCreateWithFlags(&s1, cudaStreamNonBlocking);
        cudaEventCreateWithFlags(&evFork, cudaEventDisableTiming);
        cudaEventCreateWithFlags(&evW, cudaEventDisableTiming);
        cudaEventCreateWithFlags(&evKV, cudaEventDisableTiming);
        cudaEventCreateWithFlags(&evX2, cudaEventDisableTiming);
        cudaEventCreateWithFlags(&evInit, cudaEventDisableTiming);
    }

    dim3 t256(256);
    dim3 t192(192);
    dim3 gFlash(NQ / 128, Bb * Hh);
    int nInit = (MROWS * Cc / 4 + 255) / 256;

    // ---- fork ----
    cudaEventRecord(evFork, 0);
    cudaStreamWaitEvent(s1, evFork, 0);

    // ---- stream s1: weights, mask, y-branch ----
    wconvert_all<<<(W_TOT + 255) / 256, t256, 0, s1>>>(
        qkv_w, aproj_w, q_w, k_w, v_w, cproj_w, fc1_w, fc2_w);
    cudaEventRecord(evW, s1);
    mask_detect<<<1, 256, 0, s1>>>((const unsigned int*)mask_raw);
    mask_decode<<<(NQ * NKk + 255) / 256, t256, 0, s1>>>(mask_raw);
    ln_kernel<<<MROWS, t192, 0, s1>>>(y, lny_g, lny_b, p_yln);
    gemm_tc<<<dim3(2 * Cc / 128, MROWS / 128), t256, GSM_TOTAL, s1>>>(
        p_yln, p_w + W_K, Cc, Cc, 2 * Cc,
        nullptr, nullptr, 0, nullptr, p_kvh, 0);
    {
        int n4 = (MROWS * Cc) / 4;
        copy4_kernel<<<(n4 + 255) / 256, t256, 0, s1>>>((const float4*)y,
            (float4*)(out + (size_t)MROWS * Cc), n4);
    }
    cudaEventRecord(evKV, s1);

    // ---- stream 0: x-chain ----
    ln_kernel<<<MROWS, t192>>>(x, ln1_g, ln1_b, p_ln);
    cudaStreamWaitEvent(0, evW, 0);
    gemm_tc<<<dim3(3 * Cc / 128, MROWS / 128), t256, GSM_TOTAL>>>(
        p_ln, p_w + W_QKV, Cc, Cc, 3 * Cc,
        nullptr, nullptr, 0, nullptr, p_qkvh, 0);
    flash_attn<<<gFlash, t256, FA_SMEM>>>(
        p_qkvh, p_qkvh + Cc, p_qkvh + 2 * Cc,
        (size_t)NQ * 3 * Cc, (size_t)NQ * 3 * Cc, 3 * Cc, 3 * Cc,
        nullptr, p_ao);
    gemm_tc<<<dim3(Cc / 128, MROWS / 128), t256, GSM_TOTAL>>>(
        p_ao, p_w + W_APROJ, Cc, Cc, Cc,
        aproj_b, x, 0, p_x1, nullptr, 0);

    // ---- cross attention ----
    ln_kernel<<<MROWS, t192>>>(p_x1, ln2_g, ln2_b, p_ln);
    gemm_tc<<<dim3(Cc / 128, MROWS / 128), t256, GSM_TOTAL>>>(
        p_ln, p_w + W_Q, Cc, Cc, Cc,
        nullptr, nullptr, 0, nullptr, p_qh, 0);
    cudaStreamWaitEvent(0, evKV, 0);
    flash_attn<<<gFlash, t256, FA_SMEM>>>(
        p_qh, p_kvh, p_kvh + Cc,
        (size_t)NQ * Cc, (size_t)NKk * 2 * Cc, Cc, 2 * Cc,
        p_mask, p_ao);
    gemm_tc<<<dim3(Cc / 128, MROWS / 128), t256, GSM_TOTAL>>>(
        p_ao, p_w + W_CPROJ, Cc, Cc, Cc,
        cproj_b, p_x1, 0, p_x2, nullptr, 0);
    cudaEventRecord(evX2, 0);

    // ---- s1: init fc2 output = x2 + fc2_b (overlaps ln3 + fc1) ----
    cudaStreamWaitEvent(s1, evX2, 0);
    init_out<<<nInit, t256, 0, s1>>>((const float4*)p_x2, fc2_b, (float4*)out);
    cudaEventRecord(evInit, s1);

    // ---- MLP ----
    ln_kernel<<<MROWS, t192>>>(p_x2, ln3_g, ln3_b, p_ln);
    gemm_tc<<<dim3(HID / 128, MROWS / 128), t256, GSM_TOTAL>>>(
        p_ln, p_w + W_FC1, Cc, Cc, HID,
        fc1_b, nullptr, 1, nullptr, p_h1, 0);
    cudaStreamWaitEvent(0, evInit, 0);
    gemm_tc<<<dim3(Cc / 128, MROWS / 128, 2), t256, GSM_TOTAL>>>(
        p_h1, p_w + W_FC2, HID, HID / 2, Cc,
        nullptr, nullptr, 0, out, nullptr, 1);
}